// round 2
// baseline (speedup 1.0000x reference)
#include <cuda_runtime.h>

#define B_  2
#define T_  2048
#define HD  64
#define NH  8
#define DM  512
#define ED  512
#define EV  388

// ---------------- scratch (static device allocations are allowed) ----------
__device__ float g_qh [B_*T_*HD];
__device__ float g_kh [B_*T_*HD];
__device__ float g_vh [B_*T_*HD];
__device__ float g_ctx[B_*T_*DM];
__device__ float g_hid[B_*T_*ED];

#define FMA16(ACC, A4, B4) do { \
  ACC[0][0] = fmaf(A4.x, B4.x, ACC[0][0]); \
  ACC[0][1] = fmaf(A4.x, B4.y, ACC[0][1]); \
  ACC[0][2] = fmaf(A4.x, B4.z, ACC[0][2]); \
  ACC[0][3] = fmaf(A4.x, B4.w, ACC[0][3]); \
  ACC[1][0] = fmaf(A4.y, B4.x, ACC[1][0]); \
  ACC[1][1] = fmaf(A4.y, B4.y, ACC[1][1]); \
  ACC[1][2] = fmaf(A4.y, B4.z, ACC[1][2]); \
  ACC[1][3] = fmaf(A4.y, B4.w, ACC[1][3]); \
  ACC[2][0] = fmaf(A4.z, B4.x, ACC[2][0]); \
  ACC[2][1] = fmaf(A4.z, B4.y, ACC[2][1]); \
  ACC[2][2] = fmaf(A4.z, B4.z, ACC[2][2]); \
  ACC[2][3] = fmaf(A4.z, B4.w, ACC[2][3]); \
  ACC[3][0] = fmaf(A4.w, B4.x, ACC[3][0]); \
  ACC[3][1] = fmaf(A4.w, B4.y, ACC[3][1]); \
  ACC[3][2] = fmaf(A4.w, B4.z, ACC[3][2]); \
  ACC[3][3] = fmaf(A4.w, B4.w, ACC[3][3]); \
} while (0)

// ---------------- generic tiled GEMM: C = A[MxK] * B[KxN] + bias (opt relu) --
template<bool RELU>
__launch_bounds__(256)
__global__ void gemm_bias_kernel(const float* __restrict__ A, const float* __restrict__ Bm,
                                 const float* __restrict__ bias, float* __restrict__ C,
                                 int M, int N, int K) {
  __shared__ float As[16][68];   // k-major (transposed)
  __shared__ float Bs[16][64];
  const int tid = threadIdx.x;
  const int tx = tid & 15, ty = tid >> 4;
  const int m0 = blockIdx.x * 64, n0 = blockIdx.y * 64;
  float acc[4][4] = {};
  const int am  = tid >> 2, ak4 = (tid & 3) * 4;
  const int bk  = tid >> 4, bn4 = (tid & 15) * 4;
  for (int k0 = 0; k0 < K; k0 += 16) {
    float4 a4 = make_float4(0.f, 0.f, 0.f, 0.f);
    const int arow = m0 + am;
    if (arow < M) a4 = *(const float4*)(A + (size_t)arow * K + k0 + ak4);
    As[ak4 + 0][am] = a4.x; As[ak4 + 1][am] = a4.y;
    As[ak4 + 2][am] = a4.z; As[ak4 + 3][am] = a4.w;

    float4 b4 = make_float4(0.f, 0.f, 0.f, 0.f);
    const int bcol = n0 + bn4;
    const float* brow = Bm + (size_t)(k0 + bk) * N;
    if (bcol + 3 < N) {
      b4 = *(const float4*)(brow + bcol);
    } else {
      if (bcol + 0 < N) b4.x = brow[bcol + 0];
      if (bcol + 1 < N) b4.y = brow[bcol + 1];
      if (bcol + 2 < N) b4.z = brow[bcol + 2];
    }
    *(float4*)&Bs[bk][bn4] = b4;
    __syncthreads();
#pragma unroll
    for (int kk = 0; kk < 16; kk++) {
      float4 a = *(const float4*)&As[kk][ty * 4];
      float4 b = *(const float4*)&Bs[kk][tx * 4];
      FMA16(acc, a, b);
    }
    __syncthreads();
  }
#pragma unroll
  for (int i = 0; i < 4; i++) {
    const int row = m0 + ty * 4 + i;
    if (row >= M) continue;
#pragma unroll
    for (int j = 0; j < 4; j++) {
      const int col = n0 + tx * 4 + j;
      if (col >= N) continue;
      float v = acc[i][j] + bias[col];
      if (RELU) v = fmaxf(v, 0.f);
      C[(size_t)row * N + col] = v;
    }
  }
}

// ---------------- relative-bias chunk: QE[t][slot(r)] = q[t]·E[h,r], r in [cb,cb+64)
__device__ __forceinline__ void att_chunk(const float* __restrict__ E, const float* Qs,
                                          float* PE, float* QE, int h, int cb,
                                          int tx, int ty, int tid) {
  if (cb >= T_) return;   // uniform across block: only masked positions need r>=T
  for (int i = tid; i < 4096; i += 256) {
    const int j = i >> 6, dd = i & 63;
    PE[dd * 68 + j] = E[((size_t)(h * T_ + cb + j)) * HD + dd];
  }
  __syncthreads();
  float qe[4][4] = {};
#pragma unroll 8
  for (int dd = 0; dd < 64; dd++) {
    float4 a  = *(const float4*)&Qs[dd * 68 + ty * 4];
    float4 e4 = *(const float4*)&PE[dd * 68 + tx * 4];
    FMA16(qe, a, e4);
  }
#pragma unroll
  for (int i = 0; i < 4; i++)
#pragma unroll
    for (int j = 0; j < 4; j++)
      QE[(ty * 4 + i) * 132 + ((cb + tx * 4 + j) & 127)] = qe[i][j];
  __syncthreads();
}

// ---------------- flash attention with skewed relative bias ----------------
__launch_bounds__(256, 2)
__global__ void attn_kernel(const float* __restrict__ qh, const float* __restrict__ kh,
                            const float* __restrict__ vh, const float* __restrict__ E,
                            float* __restrict__ ctx) {
  extern __shared__ float sm[];
  float* Qs = sm;               // [64][68] dim-major: Qs[dd][t]
  float* Ks = Qs + 64 * 68;     // [64][68] dim-major: Ks[dd][s]
  float* Vs = Ks + 64 * 68;     // [64][68] s-major : Vs[e][c]
  float* PE = Vs + 64 * 68;     // [64][68] dual use: E chunk (dim-major) / P^T
  float* QE = PE + 64 * 68;     // [64][132] ring buffer of Q·E^T columns

  const int tid = threadIdx.x;
  const int tx = tid & 15, ty = tid >> 4;
  const int qt = (int)gridDim.x - 1 - (int)blockIdx.x;  // heavy tiles first
  const int t0 = qt * 64;
  const int b  = blockIdx.y;
  const int h  = blockIdx.z;

  // load Q tile (pre-scaled by 1/sqrt(hd); covers both QK and bias terms)
  for (int i = tid; i < 4096; i += 256) {
    const int d = i >> 6, dd = i & 63;
    Qs[dd * 68 + d] = qh[((size_t)(b * T_ + t0 + d)) * HD + dd] * 0.125f;
  }
  __syncthreads();

  const int wbase = T_ - 64 - t0;         // first r needed (64-aligned)
  att_chunk(E, Qs, PE, QE, h, wbase,      tx, ty, tid);
  att_chunk(E, Qs, PE, QE, h, wbase + 64, tx, ty, tid);

  float mrow[4], lrow[4], O[4][4];
#pragma unroll
  for (int i = 0; i < 4; i++) {
    mrow[i] = -1e30f; lrow[i] = 0.f;
#pragma unroll
    for (int j = 0; j < 4; j++) O[i][j] = 0.f;
  }

  const int nsteps = qt + 1;
  int cnext = wbase + 128;
  for (int it = 0; it < nsteps; it++) {
    const int s0 = it * 64;
    for (int i = tid; i < 4096; i += 256) {
      const int e = i >> 6, dd = i & 63;
      const size_t gidx = ((size_t)(b * T_ + s0 + e)) * HD + dd;
      Ks[dd * 68 + e] = kh[gidx];
      Vs[e * 68 + dd] = vh[gidx];
    }
    __syncthreads();

    // QK tile
    float acc[4][4] = {};
#pragma unroll 8
    for (int dd = 0; dd < 64; dd++) {
      float4 a  = *(const float4*)&Qs[dd * 68 + ty * 4];
      float4 k4 = *(const float4*)&Ks[dd * 68 + tx * 4];
      FMA16(acc, a, k4);
    }

    // add skewed relative bias + causal mask
    float rmax[4] = {-1e30f, -1e30f, -1e30f, -1e30f};
#pragma unroll
    for (int i = 0; i < 4; i++) {
      const int t = t0 + ty * 4 + i;
#pragma unroll
      for (int j = 0; j < 4; j++) {
        const int s = s0 + tx * 4 + j;
        float sc = -1e30f;
        if (s <= t) {
          const int r = s + (T_ - 1) - t;
          sc = acc[i][j] + QE[(ty * 4 + i) * 132 + (r & 127)];
        }
        acc[i][j] = sc;
        rmax[i] = fmaxf(rmax[i], sc);
      }
    }
    // row max across the 16 threads sharing each row (same half-warp)
#pragma unroll
    for (int i = 0; i < 4; i++) {
      rmax[i] = fmaxf(rmax[i], __shfl_xor_sync(0xffffffffu, rmax[i], 1));
      rmax[i] = fmaxf(rmax[i], __shfl_xor_sync(0xffffffffu, rmax[i], 2));
      rmax[i] = fmaxf(rmax[i], __shfl_xor_sync(0xffffffffu, rmax[i], 4));
      rmax[i] = fmaxf(rmax[i], __shfl_xor_sync(0xffffffffu, rmax[i], 8));
    }
    float psum[4];
#pragma unroll
    for (int i = 0; i < 4; i++) {
      const float mnew  = fmaxf(mrow[i], rmax[i]);
      const float alpha = __expf(mrow[i] - mnew);
      mrow[i] = mnew;
      float s4 = 0.f;
#pragma unroll
      for (int j = 0; j < 4; j++) {
        const float p = __expf(acc[i][j] - mnew);   // masked -1e30 -> exp = 0
        acc[i][j] = p;
        s4 += p;
      }
      psum[i] = s4;
      lrow[i] *= alpha;
#pragma unroll
      for (int j = 0; j < 4; j++) O[i][j] *= alpha;
    }
#pragma unroll
    for (int i = 0; i < 4; i++) {
      psum[i] += __shfl_xor_sync(0xffffffffu, psum[i], 1);
      psum[i] += __shfl_xor_sync(0xffffffffu, psum[i], 2);
      psum[i] += __shfl_xor_sync(0xffffffffu, psum[i], 4);
      psum[i] += __shfl_xor_sync(0xffffffffu, psum[i], 8);
      lrow[i] += psum[i];
    }
    // write P^T for the PV GEMM
#pragma unroll
    for (int i = 0; i < 4; i++)
#pragma unroll
      for (int j = 0; j < 4; j++)
        PE[(tx * 4 + j) * 68 + ty * 4 + i] = acc[i][j];
    __syncthreads();
#pragma unroll 8
    for (int e = 0; e < 64; e++) {
      float4 p  = *(const float4*)&PE[e * 68 + ty * 4];
      float4 v4 = *(const float4*)&Vs[e * 68 + tx * 4];
      FMA16(O, p, v4);
    }
    __syncthreads();
    if (it + 1 < nsteps) { att_chunk(E, Qs, PE, QE, h, cnext, tx, ty, tid); cnext += 64; }
  }

  // epilogue: normalized, head-concatenated layout [B,T,H*hd]
#pragma unroll
  for (int i = 0; i < 4; i++) {
    const int t = t0 + ty * 4 + i;
    const float inv = 1.f / lrow[i];
    float4 o4 = make_float4(O[i][0] * inv, O[i][1] * inv, O[i][2] * inv, O[i][3] * inv);
    *(float4*)&ctx[((size_t)(b * T_ + t)) * DM + h * HD + tx * 4] = o4;
  }
}

// ---------------------------------------------------------------------------
extern "C" void kernel_launch(void* const* d_in, const int* in_sizes, int n_in,
                              void* d_out, int out_size) {
  const float* v  = (const float*)d_in[0];
  const float* k  = (const float*)d_in[1];
  const float* q  = (const float*)d_in[2];
  // d_in[3] = mask (causal tril; implicit in kernel)
  const float* Wq = (const float*)d_in[4];
  const float* bq = (const float*)d_in[5];
  const float* Wk = (const float*)d_in[6];
  const float* bk = (const float*)d_in[7];
  const float* Wv = (const float*)d_in[8];
  const float* bv = (const float*)d_in[9];
  const float* E  = (const float*)d_in[10];
  const float* Wo = (const float*)d_in[11];
  const float* bo = (const float*)d_in[12];
  const float* Wl = (const float*)d_in[13];
  const float* bl = (const float*)d_in[14];
  float* out = (float*)d_out;

  float *qh, *kh, *vh, *ctx, *hid;
  cudaGetSymbolAddress((void**)&qh,  g_qh);
  cudaGetSymbolAddress((void**)&kh,  g_kh);
  cudaGetSymbolAddress((void**)&vh,  g_vh);
  cudaGetSymbolAddress((void**)&ctx, g_ctx);
  cudaGetSymbolAddress((void**)&hid, g_hid);

  const int M = B_ * T_;
  dim3 blk(256);

  gemm_bias_kernel<false><<<dim3(M / 64, 1), blk>>>(q, Wq, bq, qh, M, HD, DM);
  gemm_bias_kernel<false><<<dim3(M / 64, 1), blk>>>(k, Wk, bk, kh, M, HD, DM);
  gemm_bias_kernel<false><<<dim3(M / 64, 1), blk>>>(v, Wv, bv, vh, M, HD, DM);

  const size_t ATT_SMEM = (size_t)(4 * 64 * 68 + 64 * 132) * sizeof(float); // 103424 B
  cudaFuncSetAttribute(attn_kernel, cudaFuncAttributeMaxDynamicSharedMemorySize,
                       (int)ATT_SMEM);
  attn_kernel<<<dim3(T_ / 64, B_, NH), blk, ATT_SMEM>>>(qh, kh, vh, E, ctx);

  gemm_bias_kernel<true ><<<dim3(M / 64, ED / 64), blk>>>(ctx, Wo, bo, hid, M, ED, DM);
  gemm_bias_kernel<false><<<dim3(M / 64, (EV + 63) / 64), blk>>>(hid, Wl, bl, out, M, EV, ED);
}

// round 3
// speedup vs baseline: 2.2920x; 2.2920x over previous
#include <cuda_runtime.h>
#include <cstdint>

#define B_  2
#define T_  2048
#define HD  64
#define NH  8
#define DM  512
#define ED  512
#define EV  388

// ---------------- scratch ----------------
__device__ float g_qh [B_*T_*HD];
__device__ float g_kh [B_*T_*HD];
__device__ float g_vh [B_*T_*HD];
__device__ float g_ctx[B_*T_*DM];
__device__ float g_hid[B_*T_*ED];

// ---------------- tf32 helpers ----------------
__device__ __forceinline__ unsigned f2tf(float f) {
  unsigned u; asm("cvt.rna.tf32.f32 %0, %1;" : "=r"(u) : "f"(f)); return u;
}
// D += A(16x8, row) * B(8x8, col) ; tf32 inputs, f32 accum
__device__ __forceinline__ void mma8(float4& d, unsigned a0, unsigned a1, unsigned a2, unsigned a3,
                                     unsigned b0, unsigned b1) {
  asm volatile("mma.sync.aligned.m16n8k8.row.col.f32.tf32.tf32.f32 "
               "{%0,%1,%2,%3}, {%4,%5,%6,%7}, {%8,%9}, {%0,%1,%2,%3};"
               : "+f"(d.x), "+f"(d.y), "+f"(d.z), "+f"(d.w)
               : "r"(a0), "r"(a1), "r"(a2), "r"(a3), "r"(b0), "r"(b1));
}

// ================= tf32-MMA GEMM: C = A[MxK] * B[KxN] + bias (opt relu) =====
// 64x64 tile / CTA, 8 warps (4x2), warp = m16 x n32, double-buffered k16 tiles.
template<bool RELU>
__device__ __forceinline__ void gemm_body(const float* __restrict__ A, const float* __restrict__ Bm,
                                          const float* __restrict__ bias, float* __restrict__ C,
                                          int M, int N, int K, int bx, int by, unsigned* sm) {
  unsigned* As = sm;           // [2][64*20]
  unsigned* Bs = sm + 2560;    // [2][16*68]
  const int tid = threadIdx.x;
  const int lane = tid & 31, wid = tid >> 5;
  const int wM = wid & 3, wN = wid >> 2;
  const int g = lane >> 2, tg = lane & 3;
  const int m0 = bx * 64, n0 = by * 64;
  const int ar = tid >> 2, ak = (tid & 3) * 4;
  const int bk = tid >> 4, bn = (tid & 15) * 4;

  { // preload tile 0
    float4 a4 = *(const float4*)(A + (size_t)(m0 + ar) * K + ak);
    As[ar*20+ak+0] = f2tf(a4.x); As[ar*20+ak+1] = f2tf(a4.y);
    As[ar*20+ak+2] = f2tf(a4.z); As[ar*20+ak+3] = f2tf(a4.w);
    const float* br = Bm + (size_t)bk * N;
    const int c = n0 + bn;
    float4 b4;
    b4.x = (c+0 < N) ? br[c+0] : 0.f; b4.y = (c+1 < N) ? br[c+1] : 0.f;
    b4.z = (c+2 < N) ? br[c+2] : 0.f; b4.w = (c+3 < N) ? br[c+3] : 0.f;
    Bs[bk*68+bn+0] = f2tf(b4.x); Bs[bk*68+bn+1] = f2tf(b4.y);
    Bs[bk*68+bn+2] = f2tf(b4.z); Bs[bk*68+bn+3] = f2tf(b4.w);
  }
  __syncthreads();

  float4 acc[4];
  acc[0] = acc[1] = acc[2] = acc[3] = make_float4(0.f, 0.f, 0.f, 0.f);

  const int NT = K >> 4;
  for (int kt = 0; kt < NT; kt++) {
    const unsigned* Ac = As + (kt & 1) * 1280;
    const unsigned* Bc = Bs + (kt & 1) * 1088;
    float4 na = make_float4(0.f,0.f,0.f,0.f), nb4 = make_float4(0.f,0.f,0.f,0.f);
    const bool has = (kt + 1 < NT);
    if (has) {
      na = *(const float4*)(A + (size_t)(m0 + ar) * K + (kt + 1) * 16 + ak);
      const float* br = Bm + (size_t)((kt + 1) * 16 + bk) * N;
      const int c = n0 + bn;
      nb4.x = (c+0 < N) ? br[c+0] : 0.f; nb4.y = (c+1 < N) ? br[c+1] : 0.f;
      nb4.z = (c+2 < N) ? br[c+2] : 0.f; nb4.w = (c+3 < N) ? br[c+3] : 0.f;
    }
#pragma unroll
    for (int kb = 0; kb < 2; kb++) {
      const int kk = kb * 8;
      const unsigned a0 = Ac[(wM*16+g  )*20 + kk+tg];
      const unsigned a1 = Ac[(wM*16+g+8)*20 + kk+tg];
      const unsigned a2 = Ac[(wM*16+g  )*20 + kk+tg+4];
      const unsigned a3 = Ac[(wM*16+g+8)*20 + kk+tg+4];
#pragma unroll
      for (int nb = 0; nb < 4; nb++) {
        const int n = wN*32 + nb*8 + g;
        mma8(acc[nb], a0, a1, a2, a3, Bc[(kk+tg)*68 + n], Bc[(kk+tg+4)*68 + n]);
      }
    }
    if (has) {
      unsigned* An = As + ((kt + 1) & 1) * 1280;
      unsigned* Bn = Bs + ((kt + 1) & 1) * 1088;
      An[ar*20+ak+0] = f2tf(na.x); An[ar*20+ak+1] = f2tf(na.y);
      An[ar*20+ak+2] = f2tf(na.z); An[ar*20+ak+3] = f2tf(na.w);
      Bn[bk*68+bn+0] = f2tf(nb4.x); Bn[bk*68+bn+1] = f2tf(nb4.y);
      Bn[bk*68+bn+2] = f2tf(nb4.z); Bn[bk*68+bn+3] = f2tf(nb4.w);
    }
    __syncthreads();
  }

#pragma unroll
  for (int nb = 0; nb < 4; nb++) {
    const int c  = n0 + wN*32 + nb*8 + 2*tg;
    const int r1 = m0 + wM*16 + g, r2 = r1 + 8;
    if (c < N) {
      const float bv = bias[c];
      float v1 = acc[nb].x + bv, v2 = acc[nb].z + bv;
      if (RELU) { v1 = fmaxf(v1, 0.f); v2 = fmaxf(v2, 0.f); }
      C[(size_t)r1 * N + c] = v1;
      C[(size_t)r2 * N + c] = v2;
    }
    if (c + 1 < N) {
      const float bv = bias[c + 1];
      float v1 = acc[nb].y + bv, v2 = acc[nb].w + bv;
      if (RELU) { v1 = fmaxf(v1, 0.f); v2 = fmaxf(v2, 0.f); }
      C[(size_t)r1 * N + c + 1] = v1;
      C[(size_t)r2 * N + c + 1] = v2;
    }
  }
}

template<bool RELU>
__launch_bounds__(256)
__global__ void gemm_mma(const float* __restrict__ A, const float* __restrict__ Bm,
                         const float* __restrict__ bias, float* __restrict__ C,
                         int M, int N, int K) {
  __shared__ unsigned sm[4736];
  gemm_body<RELU>(A, Bm, bias, C, M, N, K, blockIdx.x, blockIdx.y, sm);
}

// fused q/k/v projections (blockIdx.z selects which)
__launch_bounds__(256)
__global__ void proj_mma(const float* __restrict__ q, const float* __restrict__ k,
                         const float* __restrict__ v,
                         const float* __restrict__ Wq, const float* __restrict__ bq,
                         const float* __restrict__ Wk, const float* __restrict__ bk2,
                         const float* __restrict__ Wv, const float* __restrict__ bv2,
                         float* __restrict__ qh, float* __restrict__ kh, float* __restrict__ vh) {
  __shared__ unsigned sm[4736];
  const float* A; const float* W; const float* Bi; float* Cc;
  if (blockIdx.z == 0)      { A = q; W = Wq; Bi = bq;  Cc = qh; }
  else if (blockIdx.z == 1) { A = k; W = Wk; Bi = bk2; Cc = kh; }
  else                      { A = v; W = Wv; Bi = bv2; Cc = vh; }
  gemm_body<false>(A, W, Bi, Cc, B_*T_, HD, DM, blockIdx.x, 0, sm);
}

// ---------------- relative-bias chunk via MMA ------------------------------
// QE[t][r&127] = q[t] . E[h][r],  r in [cb, cb+64)
__device__ __forceinline__ void att_chunk_mma(const float* __restrict__ E, const unsigned* Qs,
                                              unsigned* Es, float* QE, int h, int cb,
                                              int wM, int wN, int g, int tg, int tid) {
  if (cb >= T_) return;  // uniform: only masked positions need r >= T
#pragma unroll
  for (int p = 0; p < 4; p++) {
    const int j = p * 16 + (tid >> 4);
    const int d = (tid & 15) * 4;
    float4 e4 = *(const float4*)(E + ((size_t)(h * T_ + cb + j)) * HD + d);
    uint4 u = make_uint4(f2tf(e4.x), f2tf(e4.y), f2tf(e4.z), f2tf(e4.w));
    *(uint4*)(Es + j * 68 + d) = u;
  }
  __syncthreads();
  const int lr1 = wM * 16 + g, lr2 = lr1 + 8;
  float4 acc[4];
  acc[0] = acc[1] = acc[2] = acc[3] = make_float4(0.f, 0.f, 0.f, 0.f);
#pragma unroll
  for (int kb = 0; kb < 8; kb++) {
    const int kk = kb * 8;
    const unsigned a0 = Qs[lr1*68 + kk+tg];
    const unsigned a1 = Qs[lr2*68 + kk+tg];
    const unsigned a2 = Qs[lr1*68 + kk+tg+4];
    const unsigned a3 = Qs[lr2*68 + kk+tg+4];
#pragma unroll
    for (int nb = 0; nb < 4; nb++) {
      const int n = wN*32 + nb*8 + g;
      mma8(acc[nb], a0, a1, a2, a3, Es[n*68 + kk+tg], Es[n*68 + kk+tg+4]);
    }
  }
#pragma unroll
  for (int nb = 0; nb < 4; nb++) {
    const int r = cb + wN*32 + nb*8 + 2*tg;
    QE[lr1*132 + ( r      & 127)] = acc[nb].x;
    QE[lr1*132 + ((r + 1) & 127)] = acc[nb].y;
    QE[lr2*132 + ( r      & 127)] = acc[nb].z;
    QE[lr2*132 + ((r + 1) & 127)] = acc[nb].w;
  }
  __syncthreads();
}

// ---------------- flash attention with skewed relative bias (tf32 MMA) -----
__launch_bounds__(256, 2)
__global__ void attn_kernel(const float* __restrict__ qh, const float* __restrict__ kh,
                            const float* __restrict__ vh, const float* __restrict__ E,
                            float* __restrict__ ctx) {
  extern __shared__ unsigned smu[];
  unsigned* Qs = smu;               // [64][68] tf32, row-major [t][d]
  unsigned* Ks = Qs + 64 * 68;      // [64][68] tf32, [s][d]
  unsigned* Vs = Ks + 64 * 68;      // [64][68] tf32, [s][d]
  unsigned* Ps = Vs + 64 * 68;      // [64][68] tf32, dual use: E chunk / P
  float*    QE = (float*)(Ps + 64 * 68);  // [64][132] ring buffer (fp32)
  float* sPmax = QE + 64 * 132;     // [2][64]
  float* sPsum = sPmax + 128;       // [2][64]

  const int tid = threadIdx.x;
  const int lane = tid & 31, wid = tid >> 5;
  const int wM = wid & 3, wN = wid >> 2;
  const int g = lane >> 2, tg = lane & 3;
  const int qt = (int)gridDim.x - 1 - (int)blockIdx.x;  // heavy tiles first
  const int t0 = qt * 64;
  const int b  = blockIdx.y;
  const int h  = blockIdx.z;

  // load Q tile, pre-scaled by 1/sqrt(hd), converted to tf32
#pragma unroll
  for (int p = 0; p < 4; p++) {
    const int t = p * 16 + (tid >> 4);
    const int d = (tid & 15) * 4;
    float4 q4 = *(const float4*)(qh + ((size_t)(b * T_ + t0 + t)) * HD + d);
    uint4 u = make_uint4(f2tf(q4.x * 0.125f), f2tf(q4.y * 0.125f),
                         f2tf(q4.z * 0.125f), f2tf(q4.w * 0.125f));
    *(uint4*)(Qs + t * 68 + d) = u;
  }
  // first att_chunk's internal barrier makes Qs visible before its MMA

  const int wbase = T_ - 64 - t0;
  att_chunk_mma(E, Qs, Ps, QE, h, wbase,      wM, wN, g, tg, tid);
  att_chunk_mma(E, Qs, Ps, QE, h, wbase + 64, wM, wN, g, tg, tid);

  const int lr1 = wM * 16 + g, lr2 = lr1 + 8;
  const int t1 = t0 + lr1, t2 = t0 + lr2;
  float mrow1 = -1e30f, mrow2 = -1e30f, lrow1 = 0.f, lrow2 = 0.f;
  float4 O[4];
  O[0] = O[1] = O[2] = O[3] = make_float4(0.f, 0.f, 0.f, 0.f);

  const int nsteps = qt + 1;
  int cnext = wbase + 128;
  for (int it = 0; it < nsteps; it++) {
    const int s0 = it * 64;
#pragma unroll
    for (int p = 0; p < 4; p++) {
      const int e = p * 16 + (tid >> 4);
      const int d = (tid & 15) * 4;
      const size_t gi = ((size_t)(b * T_ + s0 + e)) * HD + d;
      float4 k4 = *(const float4*)(kh + gi);
      float4 v4 = *(const float4*)(vh + gi);
      *(uint4*)(Ks + e * 68 + d) = make_uint4(f2tf(k4.x), f2tf(k4.y), f2tf(k4.z), f2tf(k4.w));
      *(uint4*)(Vs + e * 68 + d) = make_uint4(f2tf(v4.x), f2tf(v4.y), f2tf(v4.z), f2tf(v4.w));
    }
    __syncthreads();  // (A) KV ready; prev iter QE writes visible

    // ---- QK MMA ----
    float4 acc[4];
    acc[0] = acc[1] = acc[2] = acc[3] = make_float4(0.f, 0.f, 0.f, 0.f);
#pragma unroll
    for (int kb = 0; kb < 8; kb++) {
      const int kk = kb * 8;
      const unsigned a0 = Qs[lr1*68 + kk+tg];
      const unsigned a1 = Qs[lr2*68 + kk+tg];
      const unsigned a2 = Qs[lr1*68 + kk+tg+4];
      const unsigned a3 = Qs[lr2*68 + kk+tg+4];
#pragma unroll
      for (int nb = 0; nb < 4; nb++) {
        const int n = wN*32 + nb*8 + g;
        mma8(acc[nb], a0, a1, a2, a3, Ks[n*68 + kk+tg], Ks[n*68 + kk+tg+4]);
      }
    }

    // ---- bias + causal mask + partial row max ----
    float m1 = -1e30f, m2 = -1e30f;
#pragma unroll
    for (int nb = 0; nb < 4; nb++) {
      const int s = s0 + wN*32 + nb*8 + 2*tg;
      const float q0 = QE[lr1*132 + ((s     - t1 + 2047) & 127)];
      const float q1 = QE[lr1*132 + ((s + 1 - t1 + 2047) & 127)];
      const float q2 = QE[lr2*132 + ((s     - t2 + 2047) & 127)];
      const float q3 = QE[lr2*132 + ((s + 1 - t2 + 2047) & 127)];
      acc[nb].x = (s     <= t1) ? acc[nb].x + q0 : -1e30f;
      acc[nb].y = (s + 1 <= t1) ? acc[nb].y + q1 : -1e30f;
      acc[nb].z = (s     <= t2) ? acc[nb].z + q2 : -1e30f;
      acc[nb].w = (s + 1 <= t2) ? acc[nb].w + q3 : -1e30f;
      m1 = fmaxf(m1, fmaxf(acc[nb].x, acc[nb].y));
      m2 = fmaxf(m2, fmaxf(acc[nb].z, acc[nb].w));
    }
    m1 = fmaxf(m1, __shfl_xor_sync(0xffffffffu, m1, 1));
    m1 = fmaxf(m1, __shfl_xor_sync(0xffffffffu, m1, 2));
    m2 = fmaxf(m2, __shfl_xor_sync(0xffffffffu, m2, 1));
    m2 = fmaxf(m2, __shfl_xor_sync(0xffffffffu, m2, 2));
    if (tg == 0) { sPmax[wN*64 + lr1] = m1; sPmax[wN*64 + lr2] = m2; }
    __syncthreads();  // (B)

    const float M1 = fmaxf(mrow1, fmaxf(sPmax[lr1], sPmax[64 + lr1]));
    const float M2 = fmaxf(mrow2, fmaxf(sPmax[lr2], sPmax[64 + lr2]));
    const float al1 = __expf(mrow1 - M1);
    const float al2 = __expf(mrow2 - M2);
    mrow1 = M1; mrow2 = M2;
    float s1 = 0.f, s2 = 0.f;
#pragma unroll
    for (int nb = 0; nb < 4; nb++) {
      const float p0 = __expf(acc[nb].x - M1);
      const float p1 = __expf(acc[nb].y - M1);
      const float p2 = __expf(acc[nb].z - M2);
      const float p3 = __expf(acc[nb].w - M2);
      s1 += p0 + p1; s2 += p2 + p3;
      const int n = wN*32 + nb*8 + 2*tg;
      Ps[lr1*68 + n]     = f2tf(p0);
      Ps[lr1*68 + n + 1] = f2tf(p1);
      Ps[lr2*68 + n]     = f2tf(p2);
      Ps[lr2*68 + n + 1] = f2tf(p3);
      O[nb].x *= al1; O[nb].y *= al1; O[nb].z *= al2; O[nb].w *= al2;
    }
    s1 += __shfl_xor_sync(0xffffffffu, s1, 1);
    s1 += __shfl_xor_sync(0xffffffffu, s1, 2);
    s2 += __shfl_xor_sync(0xffffffffu, s2, 1);
    s2 += __shfl_xor_sync(0xffffffffu, s2, 2);
    if (tg == 0) { sPsum[wN*64 + lr1] = s1; sPsum[wN*64 + lr2] = s2; }
    lrow1 *= al1; lrow2 *= al2;
    __syncthreads();  // (C) Ps + partial sums ready
    lrow1 += sPsum[lr1] + sPsum[64 + lr1];
    lrow2 += sPsum[lr2] + sPsum[64 + lr2];

    // ---- PV MMA ----
#pragma unroll
    for (int kb = 0; kb < 8; kb++) {
      const int kk = kb * 8;
      const unsigned a0 = Ps[lr1*68 + kk+tg];
      const unsigned a1 = Ps[lr2*68 + kk+tg];
      const unsigned a2 = Ps[lr1*68 + kk+tg+4];
      const unsigned a3 = Ps[lr2*68 + kk+tg+4];
#pragma unroll
      for (int nb = 0; nb < 4; nb++) {
        const int n = wN*32 + nb*8 + g;
        mma8(O[nb], a0, a1, a2, a3, Vs[(kk+tg)*68 + n], Vs[(kk+tg+4)*68 + n]);
      }
    }
    __syncthreads();  // (D) PV done; Ps/Ks/Vs free

    if (it + 1 < nsteps) {
      att_chunk_mma(E, Qs, Ps, QE, h, cnext, wM, wN, g, tg, tid);
      cnext += 64;
    }
  }

  // epilogue: normalized, head-concatenated layout [B,T,H*hd]
  const float inv1 = 1.f / lrow1, inv2 = 1.f / lrow2;
#pragma unroll
  for (int nb = 0; nb < 4; nb++) {
    const int c = h * HD + wN*32 + nb*8 + 2*tg;
    float2 o1 = make_float2(O[nb].x * inv1, O[nb].y * inv1);
    float2 o2 = make_float2(O[nb].z * inv2, O[nb].w * inv2);
    *(float2*)&ctx[((size_t)(b * T_ + t1)) * DM + c] = o1;
    *(float2*)&ctx[((size_t)(b * T_ + t2)) * DM + c] = o2;
  }
}

// ---------------------------------------------------------------------------
extern "C" void kernel_launch(void* const* d_in, const int* in_sizes, int n_in,
                              void* d_out, int out_size) {
  const float* v  = (const float*)d_in[0];
  const float* k  = (const float*)d_in[1];
  const float* q  = (const float*)d_in[2];
  // d_in[3] = mask (causal tril; implicit)
  const float* Wq = (const float*)d_in[4];
  const float* bq = (const float*)d_in[5];
  const float* Wk = (const float*)d_in[6];
  const float* bk = (const float*)d_in[7];
  const float* Wv = (const float*)d_in[8];
  const float* bv = (const float*)d_in[9];
  const float* E  = (const float*)d_in[10];
  const float* Wo = (const float*)d_in[11];
  const float* bo = (const float*)d_in[12];
  const float* Wl = (const float*)d_in[13];
  const float* bl = (const float*)d_in[14];
  float* out = (float*)d_out;

  float *qh, *kh, *vh, *ctx, *hid;
  cudaGetSymbolAddress((void**)&qh,  g_qh);
  cudaGetSymbolAddress((void**)&kh,  g_kh);
  cudaGetSymbolAddress((void**)&vh,  g_vh);
  cudaGetSymbolAddress((void**)&ctx, g_ctx);
  cudaGetSymbolAddress((void**)&hid, g_hid);

  const int M = B_ * T_;
  dim3 blk(256);

  proj_mma<<<dim3(M / 64, 1, 3), blk>>>(q, k, v, Wq, bq, Wk, bk, Wv, bv, qh, kh, vh);

  const size_t ATT_SMEM = (size_t)(4 * 64 * 68 + 64 * 132 + 256) * sizeof(unsigned); // 104448 B
  cudaFuncSetAttribute(attn_kernel, cudaFuncAttributeMaxDynamicSharedMemorySize,
                       (int)ATT_SMEM);
  attn_kernel<<<dim3(T_ / 64, B_, NH), blk, ATT_SMEM>>>(qh, kh, vh, E, ctx);

  gemm_mma<true ><<<dim3(M / 64, ED / 64), blk>>>(ctx, Wo, bo, hid, M, ED, DM);
  gemm_mma<false><<<dim3(M / 64, (EV + 63) / 64), blk>>>(hid, Wl, bl, out, M, EV, ED);
}

// round 4
// speedup vs baseline: 2.5327x; 1.1050x over previous
#include <cuda_runtime.h>
#include <cstdint>

#define B_  2
#define T_  2048
#define HD  64
#define NH  8
#define DM  512
#define ED  512
#define EV  388

// ---------------- scratch ----------------
__device__ float g_qh [B_*T_*HD];
__device__ float g_kh [B_*T_*HD];
__device__ float g_vh [B_*T_*HD];
__device__ float g_ctx[B_*T_*DM];
__device__ float g_hid[B_*T_*ED];

// ---------------- tf32 helpers ----------------
__device__ __forceinline__ unsigned f2tf(float f) {
  unsigned u; asm("cvt.rna.tf32.f32 %0, %1;" : "=r"(u) : "f"(f)); return u;
}
// D += A(16x8, row) * B(8x8, col) ; tf32 inputs, f32 accum
__device__ __forceinline__ void mma8(float4& d, unsigned a0, unsigned a1, unsigned a2, unsigned a3,
                                     unsigned b0, unsigned b1) {
  asm volatile("mma.sync.aligned.m16n8k8.row.col.f32.tf32.tf32.f32 "
               "{%0,%1,%2,%3}, {%4,%5,%6,%7}, {%8,%9}, {%0,%1,%2,%3};"
               : "+f"(d.x), "+f"(d.y), "+f"(d.z), "+f"(d.w)
               : "r"(a0), "r"(a1), "r"(a2), "r"(a3), "r"(b0), "r"(b1));
}

// ================= tf32-MMA GEMM (verified round-3 code, unchanged) ========
template<bool RELU>
__device__ __forceinline__ void gemm_body(const float* __restrict__ A, const float* __restrict__ Bm,
                                          const float* __restrict__ bias, float* __restrict__ C,
                                          int M, int N, int K, int bx, int by, unsigned* sm) {
  unsigned* As = sm;           // [2][64*20]
  unsigned* Bs = sm + 2560;    // [2][16*68]
  const int tid = threadIdx.x;
  const int lane = tid & 31, wid = tid >> 5;
  const int wM = wid & 3, wN = wid >> 2;
  const int g = lane >> 2, tg = lane & 3;
  const int m0 = bx * 64, n0 = by * 64;
  const int ar = tid >> 2, ak = (tid & 3) * 4;
  const int bk = tid >> 4, bn = (tid & 15) * 4;

  { // preload tile 0
    float4 a4 = *(const float4*)(A + (size_t)(m0 + ar) * K + ak);
    As[ar*20+ak+0] = f2tf(a4.x); As[ar*20+ak+1] = f2tf(a4.y);
    As[ar*20+ak+2] = f2tf(a4.z); As[ar*20+ak+3] = f2tf(a4.w);
    const float* br = Bm + (size_t)bk * N;
    const int c = n0 + bn;
    float4 b4;
    b4.x = (c+0 < N) ? br[c+0] : 0.f; b4.y = (c+1 < N) ? br[c+1] : 0.f;
    b4.z = (c+2 < N) ? br[c+2] : 0.f; b4.w = (c+3 < N) ? br[c+3] : 0.f;
    Bs[bk*68+bn+0] = f2tf(b4.x); Bs[bk*68+bn+1] = f2tf(b4.y);
    Bs[bk*68+bn+2] = f2tf(b4.z); Bs[bk*68+bn+3] = f2tf(b4.w);
  }
  __syncthreads();

  float4 acc[4];
  acc[0] = acc[1] = acc[2] = acc[3] = make_float4(0.f, 0.f, 0.f, 0.f);

  const int NT = K >> 4;
  for (int kt = 0; kt < NT; kt++) {
    const unsigned* Ac = As + (kt & 1) * 1280;
    const unsigned* Bc = Bs + (kt & 1) * 1088;
    float4 na = make_float4(0.f,0.f,0.f,0.f), nb4 = make_float4(0.f,0.f,0.f,0.f);
    const bool has = (kt + 1 < NT);
    if (has) {
      na = *(const float4*)(A + (size_t)(m0 + ar) * K + (kt + 1) * 16 + ak);
      const float* br = Bm + (size_t)((kt + 1) * 16 + bk) * N;
      const int c = n0 + bn;
      nb4.x = (c+0 < N) ? br[c+0] : 0.f; nb4.y = (c+1 < N) ? br[c+1] : 0.f;
      nb4.z = (c+2 < N) ? br[c+2] : 0.f; nb4.w = (c+3 < N) ? br[c+3] : 0.f;
    }
#pragma unroll
    for (int kb = 0; kb < 2; kb++) {
      const int kk = kb * 8;
      const unsigned a0 = Ac[(wM*16+g  )*20 + kk+tg];
      const unsigned a1 = Ac[(wM*16+g+8)*20 + kk+tg];
      const unsigned a2 = Ac[(wM*16+g  )*20 + kk+tg+4];
      const unsigned a3 = Ac[(wM*16+g+8)*20 + kk+tg+4];
#pragma unroll
      for (int nb = 0; nb < 4; nb++) {
        const int n = wN*32 + nb*8 + g;
        mma8(acc[nb], a0, a1, a2, a3, Bc[(kk+tg)*68 + n], Bc[(kk+tg+4)*68 + n]);
      }
    }
    if (has) {
      unsigned* An = As + ((kt + 1) & 1) * 1280;
      unsigned* Bn = Bs + ((kt + 1) & 1) * 1088;
      An[ar*20+ak+0] = f2tf(na.x); An[ar*20+ak+1] = f2tf(na.y);
      An[ar*20+ak+2] = f2tf(na.z); An[ar*20+ak+3] = f2tf(na.w);
      Bn[bk*68+bn+0] = f2tf(nb4.x); Bn[bk*68+bn+1] = f2tf(nb4.y);
      Bn[bk*68+bn+2] = f2tf(nb4.z); Bn[bk*68+bn+3] = f2tf(nb4.w);
    }
    __syncthreads();
  }

#pragma unroll
  for (int nb = 0; nb < 4; nb++) {
    const int c  = n0 + wN*32 + nb*8 + 2*tg;
    const int r1 = m0 + wM*16 + g, r2 = r1 + 8;
    if (c < N) {
      const float bv = bias[c];
      float v1 = acc[nb].x + bv, v2 = acc[nb].z + bv;
      if (RELU) { v1 = fmaxf(v1, 0.f); v2 = fmaxf(v2, 0.f); }
      C[(size_t)r1 * N + c] = v1;
      C[(size_t)r2 * N + c] = v2;
    }
    if (c + 1 < N) {
      const float bv = bias[c + 1];
      float v1 = acc[nb].y + bv, v2 = acc[nb].w + bv;
      if (RELU) { v1 = fmaxf(v1, 0.f); v2 = fmaxf(v2, 0.f); }
      C[(size_t)r1 * N + c + 1] = v1;
      C[(size_t)r2 * N + c + 1] = v2;
    }
  }
}

template<bool RELU>
__launch_bounds__(256)
__global__ void gemm_mma(const float* __restrict__ A, const float* __restrict__ Bm,
                         const float* __restrict__ bias, float* __restrict__ C,
                         int M, int N, int K) {
  __shared__ unsigned sm[4736];
  gemm_body<RELU>(A, Bm, bias, C, M, N, K, blockIdx.x, blockIdx.y, sm);
}

__launch_bounds__(256)
__global__ void proj_mma(const float* __restrict__ q, const float* __restrict__ k,
                         const float* __restrict__ v,
                         const float* __restrict__ Wq, const float* __restrict__ bq,
                         const float* __restrict__ Wk, const float* __restrict__ bk2,
                         const float* __restrict__ Wv, const float* __restrict__ bv2,
                         float* __restrict__ qh, float* __restrict__ kh, float* __restrict__ vh) {
  __shared__ unsigned sm[4736];
  const float* A; const float* W; const float* Bi; float* Cc;
  if (blockIdx.z == 0)      { A = q; W = Wq; Bi = bq;  Cc = qh; }
  else if (blockIdx.z == 1) { A = k; W = Wk; Bi = bk2; Cc = kh; }
  else                      { A = v; W = Wv; Bi = bv2; Cc = vh; }
  gemm_body<false>(A, W, Bi, Cc, B_*T_, HD, DM, blockIdx.x, 0, sm);
}

// ===================== attention v3: s-tile 128, hoisted Q frags ===========
// warps: 2(m: wM) x 4(n: wN); warp tile m32 x n32 for QK/chunk (n over 128),
// PV uses same m-rows with n16 over head-dim 64.
// Ring: QE[t_local 0..63][r mod 256], stride 260.

struct QFrag { uint4 a[8][2]; };   // [kb][m-frag]

// chunk: QE[t][r&255] = q[t]·E[h][r] for r in [cb, cb+128)
__device__ __forceinline__ void att_chunk(const float* __restrict__ E, unsigned* Es, float* QE,
                                          const QFrag& qf, int h, int cb,
                                          int wM, int wN, int g, int tg, int tid) {
  if (cb >= T_) return;   // uniform across CTA
#pragma unroll
  for (int p = 0; p < 8; p++) {
    const int j = p * 16 + (tid >> 4);      // 0..127
    const int d = (tid & 15) * 4;
    float4 e4 = make_float4(0.f, 0.f, 0.f, 0.f);
    if (cb + j < T_)
      e4 = *(const float4*)(E + ((size_t)(h * T_ + cb + j)) * HD + d);
    *(uint4*)(Es + j * 68 + d) = make_uint4(f2tf(e4.x), f2tf(e4.y), f2tf(e4.z), f2tf(e4.w));
  }
  __syncthreads();
  float4 acc[2][4];
#pragma unroll
  for (int mf = 0; mf < 2; mf++)
#pragma unroll
    for (int nf = 0; nf < 4; nf++) acc[mf][nf] = make_float4(0.f, 0.f, 0.f, 0.f);
#pragma unroll
  for (int kb = 0; kb < 8; kb++) {
    const int kk = kb * 8;
#pragma unroll
    for (int nf = 0; nf < 4; nf++) {
      const int n = wN * 32 + nf * 8 + g;
      const unsigned b0 = Es[n * 68 + kk + tg];
      const unsigned b1 = Es[n * 68 + kk + tg + 4];
#pragma unroll
      for (int mf = 0; mf < 2; mf++)
        mma8(acc[mf][nf], qf.a[kb][mf].x, qf.a[kb][mf].y, qf.a[kb][mf].z, qf.a[kb][mf].w, b0, b1);
    }
  }
#pragma unroll
  for (int mf = 0; mf < 2; mf++) {
    const int tl = wM * 32 + mf * 16 + g;
#pragma unroll
    for (int nf = 0; nf < 4; nf++) {
      const int r = cb + wN * 32 + nf * 8 + 2 * tg;
      QE[ tl      * 260 + ( r      & 255)] = acc[mf][nf].x;
      QE[ tl      * 260 + ((r + 1) & 255)] = acc[mf][nf].y;
      QE[(tl + 8) * 260 + ( r      & 255)] = acc[mf][nf].z;
      QE[(tl + 8) * 260 + ((r + 1) & 255)] = acc[mf][nf].w;
    }
  }
  __syncthreads();
}

__launch_bounds__(256, 1)
__global__ void attn_kernel(const float* __restrict__ qh, const float* __restrict__ kh,
                            const float* __restrict__ vh, const float* __restrict__ E,
                            float* __restrict__ ctx) {
  extern __shared__ unsigned smu[];
  unsigned* Qs = smu;                     // [64][68]
  unsigned* Ks = Qs + 64 * 68;            // [128][68]
  unsigned* Vs = Ks + 128 * 68;           // [128][68]
  unsigned* Ps = Vs + 128 * 68;           // [128][68] as E-chunk / [64][132] as P
  float*    QE = (float*)(Ps + 128 * 68); // [64][260] ring
  float* sPmax = QE + 64 * 260;           // [4][64]
  float* sPsum = sPmax + 256;             // [4][64]

  const int tid = threadIdx.x;
  const int lane = tid & 31, wid = tid >> 5;
  const int wM = wid & 1, wN = wid >> 1;       // 2 x 4
  const int g = lane >> 2, tg = lane & 3;
  const int qt = (int)gridDim.x - 1 - (int)blockIdx.x;  // heavy tiles first
  const int t0 = qt * 64;
  const int b  = blockIdx.y;
  const int h  = blockIdx.z;

  // ---- load Q tile (scaled by 1/8), then hoist fragments into registers ----
#pragma unroll
  for (int p = 0; p < 4; p++) {
    const int t = p * 16 + (tid >> 4);
    const int d = (tid & 15) * 4;
    float4 q4 = *(const float4*)(qh + ((size_t)(b * T_ + t0 + t)) * HD + d);
    *(uint4*)(Qs + t * 68 + d) = make_uint4(f2tf(q4.x * 0.125f), f2tf(q4.y * 0.125f),
                                            f2tf(q4.z * 0.125f), f2tf(q4.w * 0.125f));
  }
  __syncthreads();
  QFrag qf;
#pragma unroll
  for (int kb = 0; kb < 8; kb++) {
    const int c = kb * 8 + tg;
#pragma unroll
    for (int mf = 0; mf < 2; mf++) {
      const int row = wM * 32 + mf * 16 + g;
      qf.a[kb][mf].x = Qs[ row      * 68 + c];
      qf.a[kb][mf].y = Qs[(row + 8) * 68 + c];
      qf.a[kb][mf].z = Qs[ row      * 68 + c + 4];
      qf.a[kb][mf].w = Qs[(row + 8) * 68 + c + 4];
    }
  }

  const int wbase = T_ - 64 - t0;
  att_chunk(E, Ps, QE, qf, h, wbase,       wM, wN, g, tg, tid);
  att_chunk(E, Ps, QE, qf, h, wbase + 128, wM, wN, g, tg, tid);

  // per-thread rows (shared by QK and PV mappings)
  int trow[4];
  trow[0] = wM * 32 + g;      trow[1] = trow[0] + 8;
  trow[2] = trow[0] + 16;     trow[3] = trow[0] + 24;

  float mrun[4], lrun[4];
  float4 O[2][2];   // [mf][nf] over head-dim n16 per warp
#pragma unroll
  for (int i = 0; i < 4; i++) { mrun[i] = -1e30f; lrun[i] = 0.f; }
#pragma unroll
  for (int mf = 0; mf < 2; mf++)
#pragma unroll
    for (int nf = 0; nf < 2; nf++) O[mf][nf] = make_float4(0.f, 0.f, 0.f, 0.f);

  const int ns = (t0 + 64 + 127) >> 7;
  int cnext = wbase + 256;
  for (int it = 0; it < ns; it++) {
    const int s0 = it * 128;
    // ---- load K/V s-tile (128 x 64) ----
#pragma unroll
    for (int p = 0; p < 8; p++) {
      const int e = p * 16 + (tid >> 4);
      const int d = (tid & 15) * 4;
      const size_t gi = ((size_t)(b * T_ + s0 + e)) * HD + d;
      float4 k4 = *(const float4*)(kh + gi);
      float4 v4 = *(const float4*)(vh + gi);
      *(uint4*)(Ks + e * 68 + d) = make_uint4(f2tf(k4.x), f2tf(k4.y), f2tf(k4.z), f2tf(k4.w));
      *(uint4*)(Vs + e * 68 + d) = make_uint4(f2tf(v4.x), f2tf(v4.y), f2tf(v4.z), f2tf(v4.w));
    }
    __syncthreads();  // (A)

    // ---- QK: acc[mf][nf], n over 128-wide s ----
    float4 acc[2][4];
#pragma unroll
    for (int mf = 0; mf < 2; mf++)
#pragma unroll
      for (int nf = 0; nf < 4; nf++) acc[mf][nf] = make_float4(0.f, 0.f, 0.f, 0.f);
#pragma unroll
    for (int kb = 0; kb < 8; kb++) {
      const int kk = kb * 8;
#pragma unroll
      for (int nf = 0; nf < 4; nf++) {
        const int n = wN * 32 + nf * 8 + g;
        const unsigned b0 = Ks[n * 68 + kk + tg];
        const unsigned b1 = Ks[n * 68 + kk + tg + 4];
#pragma unroll
        for (int mf = 0; mf < 2; mf++)
          mma8(acc[mf][nf], qf.a[kb][mf].x, qf.a[kb][mf].y, qf.a[kb][mf].z, qf.a[kb][mf].w, b0, b1);
      }
    }

    // ---- bias + causal mask + local row max ----
    float mx[4] = {-1e30f, -1e30f, -1e30f, -1e30f};
#pragma unroll
    for (int mf = 0; mf < 2; mf++) {
      const int tA = t0 + trow[mf * 2];
      const int tB = t0 + trow[mf * 2 + 1];
#pragma unroll
      for (int nf = 0; nf < 4; nf++) {
        const int s = s0 + wN * 32 + nf * 8 + 2 * tg;
        float4& a = acc[mf][nf];
        const float q0 = QE[ trow[mf*2]    * 260 + ((s     - tA + 2047) & 255)];
        const float q1 = QE[ trow[mf*2]    * 260 + ((s + 1 - tA + 2047) & 255)];
        const float q2 = QE[ trow[mf*2+1]  * 260 + ((s     - tB + 2047) & 255)];
        const float q3 = QE[ trow[mf*2+1]  * 260 + ((s + 1 - tB + 2047) & 255)];
        a.x = (s     <= tA) ? a.x + q0 : -1e30f;
        a.y = (s + 1 <= tA) ? a.y + q1 : -1e30f;
        a.z = (s     <= tB) ? a.z + q2 : -1e30f;
        a.w = (s + 1 <= tB) ? a.w + q3 : -1e30f;
        mx[mf*2]   = fmaxf(mx[mf*2],   fmaxf(a.x, a.y));
        mx[mf*2+1] = fmaxf(mx[mf*2+1], fmaxf(a.z, a.w));
      }
    }
#pragma unroll
    for (int i = 0; i < 4; i++) {
      mx[i] = fmaxf(mx[i], __shfl_xor_sync(0xffffffffu, mx[i], 1));
      mx[i] = fmaxf(mx[i], __shfl_xor_sync(0xffffffffu, mx[i], 2));
    }
    if (tg == 0) {
#pragma unroll
      for (int i = 0; i < 4; i++) sPmax[wN * 64 + trow[i]] = mx[i];
    }
    __syncthreads();  // (B)

    float Mrow[4], alpha[4];
#pragma unroll
    for (int i = 0; i < 4; i++) {
      float M = mrun[i];
      M = fmaxf(M, sPmax[       trow[i]]);
      M = fmaxf(M, sPmax[ 64  + trow[i]]);
      M = fmaxf(M, sPmax[128  + trow[i]]);
      M = fmaxf(M, sPmax[192  + trow[i]]);
      alpha[i] = __expf(mrun[i] - M);
      mrun[i] = M;
      Mrow[i] = M;
    }

    // ---- exp, write P (tf32), partial sums ----
    float sm4[4] = {0.f, 0.f, 0.f, 0.f};
#pragma unroll
    for (int mf = 0; mf < 2; mf++) {
#pragma unroll
      for (int nf = 0; nf < 4; nf++) {
        float4& a = acc[mf][nf];
        const int col = wN * 32 + nf * 8 + 2 * tg;
        const float p0 = __expf(a.x - Mrow[mf*2]);
        const float p1 = __expf(a.y - Mrow[mf*2]);
        const float p2 = __expf(a.z - Mrow[mf*2+1]);
        const float p3 = __expf(a.w - Mrow[mf*2+1]);
        sm4[mf*2]   += p0 + p1;
        sm4[mf*2+1] += p2 + p3;
        Ps[ trow[mf*2]    * 132 + col    ] = f2tf(p0);
        Ps[ trow[mf*2]    * 132 + col + 1] = f2tf(p1);
        Ps[ trow[mf*2+1]  * 132 + col    ] = f2tf(p2);
        Ps[ trow[mf*2+1]  * 132 + col + 1] = f2tf(p3);
      }
    }
#pragma unroll
    for (int i = 0; i < 4; i++) {
      sm4[i] += __shfl_xor_sync(0xffffffffu, sm4[i], 1);
      sm4[i] += __shfl_xor_sync(0xffffffffu, sm4[i], 2);
    }
    if (tg == 0) {
#pragma unroll
      for (int i = 0; i < 4; i++) sPsum[wN * 64 + trow[i]] = sm4[i];
    }
    __syncthreads();  // (C)
#pragma unroll
    for (int i = 0; i < 4; i++) {
      lrun[i] = lrun[i] * alpha[i]
              + sPsum[trow[i]] + sPsum[64 + trow[i]]
              + sPsum[128 + trow[i]] + sPsum[192 + trow[i]];
    }
    // rescale O
#pragma unroll
    for (int mf = 0; mf < 2; mf++)
#pragma unroll
      for (int nf = 0; nf < 2; nf++) {
        O[mf][nf].x *= alpha[mf*2];   O[mf][nf].y *= alpha[mf*2];
        O[mf][nf].z *= alpha[mf*2+1]; O[mf][nf].w *= alpha[mf*2+1];
      }

    // ---- PV: O[64x64] += P[64x128] * V[128x64]; warp n16 over head dim ----
#pragma unroll
    for (int kb = 0; kb < 16; kb++) {
      const int kk = kb * 8;
#pragma unroll
      for (int mf = 0; mf < 2; mf++) {
        const int r0 = trow[mf * 2];
        const unsigned a0 = Ps[ r0      * 132 + kk + tg];
        const unsigned a1 = Ps[(r0 + 8) * 132 + kk + tg];
        const unsigned a2 = Ps[ r0      * 132 + kk + tg + 4];
        const unsigned a3 = Ps[(r0 + 8) * 132 + kk + tg + 4];
#pragma unroll
        for (int nf = 0; nf < 2; nf++) {
          const int n = wN * 16 + nf * 8 + g;
          mma8(O[mf][nf], a0, a1, a2, a3, Vs[(kk + tg) * 68 + n], Vs[(kk + tg + 4) * 68 + n]);
        }
      }
    }
    __syncthreads();  // (D) Ps/Ks/Vs free

    if (it + 1 < ns) {
      att_chunk(E, Ps, QE, qf, h, cnext, wM, wN, g, tg, tid);
      cnext += 128;
    }
  }

  // ---- epilogue ----
  float inv[4];
#pragma unroll
  for (int i = 0; i < 4; i++) inv[i] = 1.f / lrun[i];
#pragma unroll
  for (int mf = 0; mf < 2; mf++) {
    const int tA = t0 + trow[mf * 2];
    const int tB = t0 + trow[mf * 2 + 1];
#pragma unroll
    for (int nf = 0; nf < 2; nf++) {
      const int c = h * HD + wN * 16 + nf * 8 + 2 * tg;
      float2 o1 = make_float2(O[mf][nf].x * inv[mf*2],   O[mf][nf].y * inv[mf*2]);
      float2 o2 = make_float2(O[mf][nf].z * inv[mf*2+1], O[mf][nf].w * inv[mf*2+1]);
      *(float2*)&ctx[((size_t)(b * T_ + tA)) * DM + c] = o1;
      *(float2*)&ctx[((size_t)(b * T_ + tB)) * DM + c] = o2;
    }
  }
}

// ---------------------------------------------------------------------------
extern "C" void kernel_launch(void* const* d_in, const int* in_sizes, int n_in,
                              void* d_out, int out_size) {
  const float* v  = (const float*)d_in[0];
  const float* k  = (const float*)d_in[1];
  const float* q  = (const float*)d_in[2];
  // d_in[3] = mask (causal tril; implicit)
  const float* Wq = (const float*)d_in[4];
  const float* bq = (const float*)d_in[5];
  const float* Wk = (const float*)d_in[6];
  const float* bk = (const float*)d_in[7];
  const float* Wv = (const float*)d_in[8];
  const float* bv = (const float*)d_in[9];
  const float* E  = (const float*)d_in[10];
  const float* Wo = (const float*)d_in[11];
  const float* bo = (const float*)d_in[12];
  const float* Wl = (const float*)d_in[13];
  const float* bl = (const float*)d_in[14];
  float* out = (float*)d_out;

  float *qh, *kh, *vh, *ctx, *hid;
  cudaGetSymbolAddress((void**)&qh,  g_qh);
  cudaGetSymbolAddress((void**)&kh,  g_kh);
  cudaGetSymbolAddress((void**)&vh,  g_vh);
  cudaGetSymbolAddress((void**)&ctx, g_ctx);
  cudaGetSymbolAddress((void**)&hid, g_hid);

  const int M = B_ * T_;
  dim3 blk(256);

  proj_mma<<<dim3(M / 64, 1, 3), blk>>>(q, k, v, Wq, bq, Wk, bk, Wv, bv, qh, kh, vh);

  // smem: Qs 4352 + Ks 8704 + Vs 8704 + Ps 8704 + QE 16640 + red 512 words
  const size_t ATT_SMEM = (size_t)(4352 + 8704 * 3 + 64 * 260 + 512) * 4;  // 190464 B
  cudaFuncSetAttribute(attn_kernel, cudaFuncAttributeMaxDynamicSharedMemorySize,
                       (int)ATT_SMEM);
  attn_kernel<<<dim3(T_ / 64, B_, NH), blk, ATT_SMEM>>>(qh, kh, vh, E, ctx);

  gemm_mma<true ><<<dim3(M / 64, ED / 64), blk>>>(ctx, Wo, bo, hid, M, ED, DM);
  gemm_mma<false><<<dim3(M / 64, (EV + 63) / 64), blk>>>(hid, Wl, bl, out, M, EV, ED);
}

// round 5
// speedup vs baseline: 2.6026x; 1.0276x over previous
#include <cuda_runtime.h>
#include <cstdint>

#define B_  2
#define T_  2048
#define HD  64
#define NH  8
#define DM  512
#define ED  512
#define EV  388

// ---------------- scratch ----------------
__device__ unsigned g_qh [B_*T_*HD];   // tf32 bits, pre-scaled by 0.125
__device__ unsigned g_kh [B_*T_*HD];   // tf32 bits
__device__ unsigned g_vh [B_*T_*HD];   // tf32 bits
__device__ unsigned g_Etf[NH*T_*HD];   // tf32 bits
__device__ float    g_ctx[B_*T_*DM];
__device__ float    g_hid[B_*T_*ED];

// ---------------- tf32 / async helpers ----------------
__device__ __forceinline__ unsigned f2tf(float f) {
  unsigned u; asm("cvt.rna.tf32.f32 %0, %1;" : "=r"(u) : "f"(f)); return u;
}
__device__ __forceinline__ void mma8(float4& d, unsigned a0, unsigned a1, unsigned a2, unsigned a3,
                                     unsigned b0, unsigned b1) {
  asm volatile("mma.sync.aligned.m16n8k8.row.col.f32.tf32.tf32.f32 "
               "{%0,%1,%2,%3}, {%4,%5,%6,%7}, {%8,%9}, {%0,%1,%2,%3};"
               : "+f"(d.x), "+f"(d.y), "+f"(d.z), "+f"(d.w)
               : "r"(a0), "r"(a1), "r"(a2), "r"(a3), "r"(b0), "r"(b1));
}
__device__ __forceinline__ void cpa16(unsigned smem, const void* g) {
  asm volatile("cp.async.cg.shared.global [%0], [%1], 16;" :: "r"(smem), "l"(g));
}
__device__ __forceinline__ void cpa_wait() {
  asm volatile("cp.async.commit_group;");
  asm volatile("cp.async.wait_group 0;" ::: "memory");
}

// ================= tf32-MMA GEMM v2: 128x64 CTA tile =======================
// 8 warps as 4(m) x 2(n); warp m32 x n32; double-buffered k16.
// TF32OUT: write f2tf(v * oscale) bits instead of float.
template<bool RELU, bool TF32OUT>
__device__ __forceinline__ void gemm2_body(const float* __restrict__ A, const float* __restrict__ Bm,
                                           const float* __restrict__ bias, void* __restrict__ Cv,
                                           int M, int N, int K, float oscale,
                                           int bx, int by, unsigned* sm) {
  unsigned* As = sm;           // [2][128*20]
  unsigned* Bs = sm + 5120;    // [2][16*68]
  const int tid = threadIdx.x;
  const int lane = tid & 31, wid = tid >> 5;
  const int wM = wid & 3, wN = wid >> 2;
  const int g = lane >> 2, tg = lane & 3;
  const int m0 = bx * 128, n0 = by * 64;
  const int ai0 = tid * 2, ai1 = tid * 2 + 1;
  const int ar0 = ai0 >> 2, ac0 = (ai0 & 3) * 4;
  const int ar1 = ai1 >> 2, ac1 = (ai1 & 3) * 4;
  const int bk = tid >> 4, bn = (tid & 15) * 4;

  { // preload tile 0
    float4 a4 = *(const float4*)(A + (size_t)(m0 + ar0) * K + ac0);
    As[ar0*20+ac0+0] = f2tf(a4.x); As[ar0*20+ac0+1] = f2tf(a4.y);
    As[ar0*20+ac0+2] = f2tf(a4.z); As[ar0*20+ac0+3] = f2tf(a4.w);
    a4 = *(const float4*)(A + (size_t)(m0 + ar1) * K + ac1);
    As[ar1*20+ac1+0] = f2tf(a4.x); As[ar1*20+ac1+1] = f2tf(a4.y);
    As[ar1*20+ac1+2] = f2tf(a4.z); As[ar1*20+ac1+3] = f2tf(a4.w);
    const float* br = Bm + (size_t)bk * N;
    const int c = n0 + bn;
    float4 b4;
    b4.x = (c+0 < N) ? br[c+0] : 0.f; b4.y = (c+1 < N) ? br[c+1] : 0.f;
    b4.z = (c+2 < N) ? br[c+2] : 0.f; b4.w = (c+3 < N) ? br[c+3] : 0.f;
    Bs[bk*68+bn+0] = f2tf(b4.x); Bs[bk*68+bn+1] = f2tf(b4.y);
    Bs[bk*68+bn+2] = f2tf(b4.z); Bs[bk*68+bn+3] = f2tf(b4.w);
  }
  __syncthreads();

  float4 acc[2][4];
#pragma unroll
  for (int mf = 0; mf < 2; mf++)
#pragma unroll
    for (int nf = 0; nf < 4; nf++) acc[mf][nf] = make_float4(0.f, 0.f, 0.f, 0.f);

  const int NT = K >> 4;
  for (int kt = 0; kt < NT; kt++) {
    const unsigned* Ac = As + (kt & 1) * 2560;
    const unsigned* Bc = Bs + (kt & 1) * 1088;
    float4 na0 = make_float4(0.f,0.f,0.f,0.f), na1 = na0, nb4 = na0;
    const bool has = (kt + 1 < NT);
    if (has) {
      na0 = *(const float4*)(A + (size_t)(m0 + ar0) * K + (kt + 1) * 16 + ac0);
      na1 = *(const float4*)(A + (size_t)(m0 + ar1) * K + (kt + 1) * 16 + ac1);
      const float* br = Bm + (size_t)((kt + 1) * 16 + bk) * N;
      const int c = n0 + bn;
      nb4.x = (c+0 < N) ? br[c+0] : 0.f; nb4.y = (c+1 < N) ? br[c+1] : 0.f;
      nb4.z = (c+2 < N) ? br[c+2] : 0.f; nb4.w = (c+3 < N) ? br[c+3] : 0.f;
    }
#pragma unroll
    for (int kb = 0; kb < 2; kb++) {
      const int kk = kb * 8;
      uint4 af[2];
#pragma unroll
      for (int mf = 0; mf < 2; mf++) {
        const int r = wM * 32 + mf * 16 + g;
        af[mf].x = Ac[ r      * 20 + kk + tg];
        af[mf].y = Ac[(r + 8) * 20 + kk + tg];
        af[mf].z = Ac[ r      * 20 + kk + tg + 4];
        af[mf].w = Ac[(r + 8) * 20 + kk + tg + 4];
      }
#pragma unroll
      for (int nf = 0; nf < 4; nf++) {
        const int n = wN * 32 + nf * 8 + g;
        const unsigned b0 = Bc[(kk + tg) * 68 + n];
        const unsigned b1 = Bc[(kk + tg + 4) * 68 + n];
#pragma unroll
        for (int mf = 0; mf < 2; mf++)
          mma8(acc[mf][nf], af[mf].x, af[mf].y, af[mf].z, af[mf].w, b0, b1);
      }
    }
    if (has) {
      unsigned* An = As + ((kt + 1) & 1) * 2560;
      unsigned* Bn = Bs + ((kt + 1) & 1) * 1088;
      An[ar0*20+ac0+0] = f2tf(na0.x); An[ar0*20+ac0+1] = f2tf(na0.y);
      An[ar0*20+ac0+2] = f2tf(na0.z); An[ar0*20+ac0+3] = f2tf(na0.w);
      An[ar1*20+ac1+0] = f2tf(na1.x); An[ar1*20+ac1+1] = f2tf(na1.y);
      An[ar1*20+ac1+2] = f2tf(na1.z); An[ar1*20+ac1+3] = f2tf(na1.w);
      Bn[bk*68+bn+0] = f2tf(nb4.x); Bn[bk*68+bn+1] = f2tf(nb4.y);
      Bn[bk*68+bn+2] = f2tf(nb4.z); Bn[bk*68+bn+3] = f2tf(nb4.w);
    }
    __syncthreads();
  }

#pragma unroll
  for (int mf = 0; mf < 2; mf++) {
    const int r1 = m0 + wM * 32 + mf * 16 + g, r2 = r1 + 8;
#pragma unroll
    for (int nf = 0; nf < 4; nf++) {
      const int c = n0 + wN * 32 + nf * 8 + 2 * tg;
      const float4 a = acc[mf][nf];
      if (c < N) {
        const float bv = bias[c];
        float v1 = a.x + bv, v2 = a.z + bv;
        if (RELU) { v1 = fmaxf(v1, 0.f); v2 = fmaxf(v2, 0.f); }
        if (TF32OUT) {
          ((unsigned*)Cv)[(size_t)r1 * N + c] = f2tf(v1 * oscale);
          ((unsigned*)Cv)[(size_t)r2 * N + c] = f2tf(v2 * oscale);
        } else {
          ((float*)Cv)[(size_t)r1 * N + c] = v1;
          ((float*)Cv)[(size_t)r2 * N + c] = v2;
        }
      }
      if (c + 1 < N) {
        const float bv = bias[c + 1];
        float v1 = a.y + bv, v2 = a.w + bv;
        if (RELU) { v1 = fmaxf(v1, 0.f); v2 = fmaxf(v2, 0.f); }
        if (TF32OUT) {
          ((unsigned*)Cv)[(size_t)r1 * N + c + 1] = f2tf(v1 * oscale);
          ((unsigned*)Cv)[(size_t)r2 * N + c + 1] = f2tf(v2 * oscale);
        } else {
          ((float*)Cv)[(size_t)r1 * N + c + 1] = v1;
          ((float*)Cv)[(size_t)r2 * N + c + 1] = v2;
        }
      }
    }
  }
}

template<bool RELU>
__launch_bounds__(256)
__global__ void gemm2(const float* __restrict__ A, const float* __restrict__ Bm,
                      const float* __restrict__ bias, float* __restrict__ C,
                      int M, int N, int K) {
  __shared__ unsigned sm[7296];
  gemm2_body<RELU, false>(A, Bm, bias, C, M, N, K, 1.f, blockIdx.x, blockIdx.y, sm);
}

// fused q/k/v projections -> tf32-bit outputs (q pre-scaled by 0.125)
__launch_bounds__(256)
__global__ void proj2(const float* __restrict__ q, const float* __restrict__ k,
                      const float* __restrict__ v,
                      const float* __restrict__ Wq, const float* __restrict__ bq,
                      const float* __restrict__ Wk, const float* __restrict__ bk2,
                      const float* __restrict__ Wv, const float* __restrict__ bv2,
                      unsigned* __restrict__ qh, unsigned* __restrict__ kh,
                      unsigned* __restrict__ vh) {
  __shared__ unsigned sm[7296];
  const float* A; const float* W; const float* Bi; unsigned* Cc; float sc;
  if (blockIdx.z == 0)      { A = q; W = Wq; Bi = bq;  Cc = qh; sc = 0.125f; }
  else if (blockIdx.z == 1) { A = k; W = Wk; Bi = bk2; Cc = kh; sc = 1.f; }
  else                      { A = v; W = Wv; Bi = bv2; Cc = vh; sc = 1.f; }
  gemm2_body<false, true>(A, W, Bi, Cc, B_*T_, HD, DM, sc, blockIdx.x, 0, sm);
}

// one-shot E -> tf32 bits
__global__ void e2tf_kernel(const float* __restrict__ E, unsigned* __restrict__ Etf) {
  const int i = (blockIdx.x * 256 + threadIdx.x) * 4;
  float4 e = *(const float4*)(E + i);
  *(uint4*)(Etf + i) = make_uint4(f2tf(e.x), f2tf(e.y), f2tf(e.z), f2tf(e.w));
}

// ===================== attention: s-tile 128, hoisted Q frags ==============
struct QFrag { uint4 a[8][2]; };   // [kb][m-frag]

// QE[t][r&255] = q[t]·E[h][r] for r in [cb, cb+128)
__device__ __forceinline__ void att_chunk(const unsigned* __restrict__ Etf, unsigned* Es, float* QE,
                                          const QFrag& qf, int h, int cb,
                                          int wM, int wN, int g, int tg, int tid) {
  if (cb >= T_) return;   // uniform across CTA
  const unsigned es_s = (unsigned)__cvta_generic_to_shared(Es);
#pragma unroll
  for (int p = 0; p < 8; p++) {
    const int j = p * 16 + (tid >> 4);      // 0..127
    const int d = (tid & 15) * 4;
    if (cb + j < T_)
      cpa16(es_s + (unsigned)(j * 68 + d) * 4u, Etf + ((size_t)(h * T_ + cb + j)) * HD + d);
    else
      *(uint4*)(Es + j * 68 + d) = make_uint4(0u, 0u, 0u, 0u);
  }
  cpa_wait();
  __syncthreads();
  float4 acc[2][4];
#pragma unroll
  for (int mf = 0; mf < 2; mf++)
#pragma unroll
    for (int nf = 0; nf < 4; nf++) acc[mf][nf] = make_float4(0.f, 0.f, 0.f, 0.f);
#pragma unroll
  for (int kb = 0; kb < 8; kb++) {
    const int kk = kb * 8;
#pragma unroll
    for (int nf = 0; nf < 4; nf++) {
      const int n = wN * 32 + nf * 8 + g;
      const unsigned b0 = Es[n * 68 + kk + tg];
      const unsigned b1 = Es[n * 68 + kk + tg + 4];
#pragma unroll
      for (int mf = 0; mf < 2; mf++)
        mma8(acc[mf][nf], qf.a[kb][mf].x, qf.a[kb][mf].y, qf.a[kb][mf].z, qf.a[kb][mf].w, b0, b1);
    }
  }
#pragma unroll
  for (int mf = 0; mf < 2; mf++) {
    const int tl = wM * 32 + mf * 16 + g;
#pragma unroll
    for (int nf = 0; nf < 4; nf++) {
      const int r = cb + wN * 32 + nf * 8 + 2 * tg;
      QE[ tl      * 260 + ( r      & 255)] = acc[mf][nf].x;
      QE[ tl      * 260 + ((r + 1) & 255)] = acc[mf][nf].y;
      QE[(tl + 8) * 260 + ( r      & 255)] = acc[mf][nf].z;
      QE[(tl + 8) * 260 + ((r + 1) & 255)] = acc[mf][nf].w;
    }
  }
  __syncthreads();
}

__launch_bounds__(256, 1)
__global__ void attn_kernel(const unsigned* __restrict__ qh, const unsigned* __restrict__ kh,
                            const unsigned* __restrict__ vh, const unsigned* __restrict__ Etf,
                            float* __restrict__ ctx) {
  extern __shared__ unsigned smu[];
  unsigned* Qs = smu;                     // [64][68]
  unsigned* Ks = Qs + 64 * 68;            // [128][68]
  unsigned* Vs = Ks + 128 * 68;           // [128][68]
  unsigned* Ps = Vs + 128 * 68;           // [128][68] as E-chunk / [64][132] as P
  float*    QE = (float*)(Ps + 128 * 68); // [64][260] ring
  float* sPmax = QE + 64 * 260;           // [4][64]
  float* sPsum = sPmax + 256;             // [4][64]

  const int tid = threadIdx.x;
  const int lane = tid & 31, wid = tid >> 5;
  const int wM = wid & 1, wN = wid >> 1;       // 2 x 4
  const int g = lane >> 2, tg = lane & 3;
  const int qt = (int)gridDim.x - 1 - (int)blockIdx.x;  // heavy tiles first
  const int t0 = qt * 64;
  const int b  = blockIdx.y;
  const int h  = blockIdx.z;

  // ---- load Q tile (already tf32 bits, pre-scaled) ----
  {
    const unsigned qs_s = (unsigned)__cvta_generic_to_shared(Qs);
#pragma unroll
    for (int p = 0; p < 4; p++) {
      const int t = p * 16 + (tid >> 4);
      const int d = (tid & 15) * 4;
      cpa16(qs_s + (unsigned)(t * 68 + d) * 4u, qh + ((size_t)(b * T_ + t0 + t)) * HD + d);
    }
    cpa_wait();
  }
  __syncthreads();
  QFrag qf;
#pragma unroll
  for (int kb = 0; kb < 8; kb++) {
    const int c = kb * 8 + tg;
#pragma unroll
    for (int mf = 0; mf < 2; mf++) {
      const int row = wM * 32 + mf * 16 + g;
      qf.a[kb][mf].x = Qs[ row      * 68 + c];
      qf.a[kb][mf].y = Qs[(row + 8) * 68 + c];
      qf.a[kb][mf].z = Qs[ row      * 68 + c + 4];
      qf.a[kb][mf].w = Qs[(row + 8) * 68 + c + 4];
    }
  }

  const int wbase = T_ - 64 - t0;
  att_chunk(Etf, Ps, QE, qf, h, wbase,       wM, wN, g, tg, tid);
  att_chunk(Etf, Ps, QE, qf, h, wbase + 128, wM, wN, g, tg, tid);

  int trow[4];
  trow[0] = wM * 32 + g;      trow[1] = trow[0] + 8;
  trow[2] = trow[0] + 16;     trow[3] = trow[0] + 24;

  float mrun[4], lrun[4];
  float4 O[2][2];
#pragma unroll
  for (int i = 0; i < 4; i++) { mrun[i] = -1e30f; lrun[i] = 0.f; }
#pragma unroll
  for (int mf = 0; mf < 2; mf++)
#pragma unroll
    for (int nf = 0; nf < 2; nf++) O[mf][nf] = make_float4(0.f, 0.f, 0.f, 0.f);

  const unsigned ks_s = (unsigned)__cvta_generic_to_shared(Ks);
  const unsigned vs_s = (unsigned)__cvta_generic_to_shared(Vs);

  const int ns = (t0 + 64 + 127) >> 7;
  int cnext = wbase + 256;
  for (int it = 0; it < ns; it++) {
    const int s0 = it * 128;
    // ---- async load K/V s-tile (128 x 64, tf32 bits) ----
#pragma unroll
    for (int p = 0; p < 8; p++) {
      const int e = p * 16 + (tid >> 4);
      const int d = (tid & 15) * 4;
      const size_t gi = ((size_t)(b * T_ + s0 + e)) * HD + d;
      const unsigned so = (unsigned)(e * 68 + d) * 4u;
      cpa16(ks_s + so, kh + gi);
      cpa16(vs_s + so, vh + gi);
    }
    cpa_wait();
    __syncthreads();  // (A)

    // ---- QK ----
    float4 acc[2][4];
#pragma unroll
    for (int mf = 0; mf < 2; mf++)
#pragma unroll
      for (int nf = 0; nf < 4; nf++) acc[mf][nf] = make_float4(0.f, 0.f, 0.f, 0.f);
#pragma unroll
    for (int kb = 0; kb < 8; kb++) {
      const int kk = kb * 8;
#pragma unroll
      for (int nf = 0; nf < 4; nf++) {
        const int n = wN * 32 + nf * 8 + g;
        const unsigned b0 = Ks[n * 68 + kk + tg];
        const unsigned b1 = Ks[n * 68 + kk + tg + 4];
#pragma unroll
        for (int mf = 0; mf < 2; mf++)
          mma8(acc[mf][nf], qf.a[kb][mf].x, qf.a[kb][mf].y, qf.a[kb][mf].z, qf.a[kb][mf].w, b0, b1);
      }
    }

    // ---- bias + causal mask + local row max ----
    float mx[4] = {-1e30f, -1e30f, -1e30f, -1e30f};
#pragma unroll
    for (int mf = 0; mf < 2; mf++) {
      const int tA = t0 + trow[mf * 2];
      const int tB = t0 + trow[mf * 2 + 1];
#pragma unroll
      for (int nf = 0; nf < 4; nf++) {
        const int s = s0 + wN * 32 + nf * 8 + 2 * tg;
        float4& a = acc[mf][nf];
        const float q0 = QE[ trow[mf*2]    * 260 + ((s     - tA + 2047) & 255)];
        const float q1 = QE[ trow[mf*2]    * 260 + ((s + 1 - tA + 2047) & 255)];
        const float q2 = QE[ trow[mf*2+1]  * 260 + ((s     - tB + 2047) & 255)];
        const float q3 = QE[ trow[mf*2+1]  * 260 + ((s + 1 - tB + 2047) & 255)];
        a.x = (s     <= tA) ? a.x + q0 : -1e30f;
        a.y = (s + 1 <= tA) ? a.y + q1 : -1e30f;
        a.z = (s     <= tB) ? a.z + q2 : -1e30f;
        a.w = (s + 1 <= tB) ? a.w + q3 : -1e30f;
        mx[mf*2]   = fmaxf(mx[mf*2],   fmaxf(a.x, a.y));
        mx[mf*2+1] = fmaxf(mx[mf*2+1], fmaxf(a.z, a.w));
      }
    }
#pragma unroll
    for (int i = 0; i < 4; i++) {
      mx[i] = fmaxf(mx[i], __shfl_xor_sync(0xffffffffu, mx[i], 1));
      mx[i] = fmaxf(mx[i], __shfl_xor_sync(0xffffffffu, mx[i], 2));
    }
    if (tg == 0) {
#pragma unroll
      for (int i = 0; i < 4; i++) sPmax[wN * 64 + trow[i]] = mx[i];
    }
    __syncthreads();  // (B)

    float Mrow[4], alpha[4];
#pragma unroll
    for (int i = 0; i < 4; i++) {
      float M = mrun[i];
      M = fmaxf(M, sPmax[       trow[i]]);
      M = fmaxf(M, sPmax[ 64  + trow[i]]);
      M = fmaxf(M, sPmax[128  + trow[i]]);
      M = fmaxf(M, sPmax[192  + trow[i]]);
      alpha[i] = __expf(mrun[i] - M);
      mrun[i] = M;
      Mrow[i] = M;
    }

    float sm4[4] = {0.f, 0.f, 0.f, 0.f};
#pragma unroll
    for (int mf = 0; mf < 2; mf++) {
#pragma unroll
      for (int nf = 0; nf < 4; nf++) {
        float4& a = acc[mf][nf];
        const int col = wN * 32 + nf * 8 + 2 * tg;
        const float p0 = __expf(a.x - Mrow[mf*2]);
        const float p1 = __expf(a.y - Mrow[mf*2]);
        const float p2 = __expf(a.z - Mrow[mf*2+1]);
        const float p3 = __expf(a.w - Mrow[mf*2+1]);
        sm4[mf*2]   += p0 + p1;
        sm4[mf*2+1] += p2 + p3;
        Ps[ trow[mf*2]    * 132 + col    ] = f2tf(p0);
        Ps[ trow[mf*2]    * 132 + col + 1] = f2tf(p1);
        Ps[ trow[mf*2+1]  * 132 + col    ] = f2tf(p2);
        Ps[ trow[mf*2+1]  * 132 + col + 1] = f2tf(p3);
      }
    }
#pragma unroll
    for (int i = 0; i < 4; i++) {
      sm4[i] += __shfl_xor_sync(0xffffffffu, sm4[i], 1);
      sm4[i] += __shfl_xor_sync(0xffffffffu, sm4[i], 2);
    }
    if (tg == 0) {
#pragma unroll
      for (int i = 0; i < 4; i++) sPsum[wN * 64 + trow[i]] = sm4[i];
    }
    __syncthreads();  // (C)
#pragma unroll
    for (int i = 0; i < 4; i++) {
      lrun[i] = lrun[i] * alpha[i]
              + sPsum[trow[i]] + sPsum[64 + trow[i]]
              + sPsum[128 + trow[i]] + sPsum[192 + trow[i]];
    }
#pragma unroll
    for (int mf = 0; mf < 2; mf++)
#pragma unroll
      for (int nf = 0; nf < 2; nf++) {
        O[mf][nf].x *= alpha[mf*2];   O[mf][nf].y *= alpha[mf*2];
        O[mf][nf].z *= alpha[mf*2+1]; O[mf][nf].w *= alpha[mf*2+1];
      }

    // ---- PV ----
#pragma unroll
    for (int kb = 0; kb < 16; kb++) {
      const int kk = kb * 8;
#pragma unroll
      for (int mf = 0; mf < 2; mf++) {
        const int r0 = trow[mf * 2];
        const unsigned a0 = Ps[ r0      * 132 + kk + tg];
        const unsigned a1 = Ps[(r0 + 8) * 132 + kk + tg];
        const unsigned a2 = Ps[ r0      * 132 + kk + tg + 4];
        const unsigned a3 = Ps[(r0 + 8) * 132 + kk + tg + 4];
#pragma unroll
        for (int nf = 0; nf < 2; nf++) {
          const int n = wN * 16 + nf * 8 + g;
          mma8(O[mf][nf], a0, a1, a2, a3, Vs[(kk + tg) * 68 + n], Vs[(kk + tg + 4) * 68 + n]);
        }
      }
    }
    __syncthreads();  // (D)

    if (it + 1 < ns) {
      att_chunk(Etf, Ps, QE, qf, h, cnext, wM, wN, g, tg, tid);
      cnext += 128;
    }
  }

  // ---- epilogue ----
  float inv[4];
#pragma unroll
  for (int i = 0; i < 4; i++) inv[i] = 1.f / lrun[i];
#pragma unroll
  for (int mf = 0; mf < 2; mf++) {
    const int tA = t0 + trow[mf * 2];
    const int tB = t0 + trow[mf * 2 + 1];
#pragma unroll
    for (int nf = 0; nf < 2; nf++) {
      const int c = h * HD + wN * 16 + nf * 8 + 2 * tg;
      float2 o1 = make_float2(O[mf][nf].x * inv[mf*2],   O[mf][nf].y * inv[mf*2]);
      float2 o2 = make_float2(O[mf][nf].z * inv[mf*2+1], O[mf][nf].w * inv[mf*2+1]);
      *(float2*)&ctx[((size_t)(b * T_ + tA)) * DM + c] = o1;
      *(float2*)&ctx[((size_t)(b * T_ + tB)) * DM + c] = o2;
    }
  }
}

// ---------------------------------------------------------------------------
extern "C" void kernel_launch(void* const* d_in, const int* in_sizes, int n_in,
                              void* d_out, int out_size) {
  const float* v  = (const float*)d_in[0];
  const float* k  = (const float*)d_in[1];
  const float* q  = (const float*)d_in[2];
  // d_in[3] = mask (causal tril; implicit)
  const float* Wq = (const float*)d_in[4];
  const float* bq = (const float*)d_in[5];
  const float* Wk = (const float*)d_in[6];
  const float* bk = (const float*)d_in[7];
  const float* Wv = (const float*)d_in[8];
  const float* bv = (const float*)d_in[9];
  const float* E  = (const float*)d_in[10];
  const float* Wo = (const float*)d_in[11];
  const float* bo = (const float*)d_in[12];
  const float* Wl = (const float*)d_in[13];
  const float* bl = (const float*)d_in[14];
  float* out = (float*)d_out;

  unsigned *qh, *kh, *vh, *Etf;
  float *ctx, *hid;
  cudaGetSymbolAddress((void**)&qh,  g_qh);
  cudaGetSymbolAddress((void**)&kh,  g_kh);
  cudaGetSymbolAddress((void**)&vh,  g_vh);
  cudaGetSymbolAddress((void**)&Etf, g_Etf);
  cudaGetSymbolAddress((void**)&ctx, g_ctx);
  cudaGetSymbolAddress((void**)&hid, g_hid);

  const int M = B_ * T_;
  dim3 blk(256);

  e2tf_kernel<<<NH * T_ * HD / 1024, 256>>>(E, Etf);
  proj2<<<dim3(M / 128, 1, 3), blk>>>(q, k, v, Wq, bq, Wk, bk, Wv, bv, qh, kh, vh);

  const size_t ATT_SMEM = (size_t)(4352 + 8704 * 3 + 64 * 260 + 512) * 4;  // 190464 B
  cudaFuncSetAttribute(attn_kernel, cudaFuncAttributeMaxDynamicSharedMemorySize,
                       (int)ATT_SMEM);
  attn_kernel<<<dim3(T_ / 64, B_, NH), blk, ATT_SMEM>>>(qh, kh, vh, Etf, ctx);

  gemm2<true ><<<dim3(M / 128, ED / 64), blk>>>(ctx, Wo, bo, hid, M, ED, DM);
  gemm2<false><<<dim3(M / 128, (EV + 63) / 64), blk>>>(hid, Wl, bl, out, M, EV, ED);
}

// round 6
// speedup vs baseline: 2.9280x; 1.1250x over previous
#include <cuda_runtime.h>
#include <cstdint>

#define B_  2
#define T_  2048
#define HD  64
#define NH  8
#define DM  512
#define ED  512
#define EV  388
#define EVP 448      // Wl padded width

// ---------------- scratch ----------------
__device__ unsigned g_qh  [B_*T_*HD];   // tf32 bits, pre-scaled by 0.125
__device__ unsigned g_kh  [B_*T_*HD];   // tf32 bits
__device__ unsigned g_vh  [B_*T_*HD];   // tf32 bits
__device__ unsigned g_Etf [NH*T_*HD];   // tf32 bits
__device__ unsigned g_Wotf[DM*ED];      // tf32 bits
__device__ unsigned g_Wltf[ED*EVP];     // tf32 bits, zero-padded cols
__device__ unsigned g_ctx [B_*T_*DM];   // tf32 bits (attn out)
__device__ unsigned g_hid [B_*T_*ED];   // tf32 bits (relu out)

// ---------------- tf32 / async helpers ----------------
__device__ __forceinline__ unsigned f2tf(float f) {
  unsigned u; asm("cvt.rna.tf32.f32 %0, %1;" : "=r"(u) : "f"(f)); return u;
}
__device__ __forceinline__ void mma8(float4& d, unsigned a0, unsigned a1, unsigned a2, unsigned a3,
                                     unsigned b0, unsigned b1) {
  asm volatile("mma.sync.aligned.m16n8k8.row.col.f32.tf32.tf32.f32 "
               "{%0,%1,%2,%3}, {%4,%5,%6,%7}, {%8,%9}, {%0,%1,%2,%3};"
               : "+f"(d.x), "+f"(d.y), "+f"(d.z), "+f"(d.w)
               : "r"(a0), "r"(a1), "r"(a2), "r"(a3), "r"(b0), "r"(b1));
}
__device__ __forceinline__ void cpa16(unsigned smem, const void* g) {
  asm volatile("cp.async.cg.shared.global [%0], [%1], 16;" :: "r"(smem), "l"(g));
}
#define CPA_COMMIT() asm volatile("cp.async.commit_group;")
#define CPA_WAIT(N)  asm volatile("cp.async.wait_group %0;" :: "n"(N) : "memory")
__device__ __forceinline__ void cpa_wait_all() {
  CPA_COMMIT(); CPA_WAIT(0);
}

// ---------------- one-shot converters ----------------
__global__ void cvt4_kernel(const float* __restrict__ s, unsigned* __restrict__ d, int n4) {
  const int i = blockIdx.x * 256 + threadIdx.x;
  if (i < n4) {
    float4 f = ((const float4*)s)[i];
    ((uint4*)d)[i] = make_uint4(f2tf(f.x), f2tf(f.y), f2tf(f.z), f2tf(f.w));
  }
}
__global__ void cvtpad_kernel(const float* __restrict__ s, unsigned* __restrict__ d) {
  const int i = blockIdx.x * 256 + threadIdx.x;   // over ED*EVP
  const int k = i / EVP, n = i % EVP;
  d[i] = (n < EV) ? f2tf(s[k * EV + n]) : 0u;
}

// ================= proj GEMM (verified r5 gemm2_body, float-in) ============
template<bool RELU, bool TF32OUT>
__device__ __forceinline__ void gemm2_body(const float* __restrict__ A, const float* __restrict__ Bm,
                                           const float* __restrict__ bias, void* __restrict__ Cv,
                                           int M, int N, int K, float oscale,
                                           int bx, int by, unsigned* sm) {
  unsigned* As = sm;           // [2][128*20]
  unsigned* Bs = sm + 5120;    // [2][16*68]
  const int tid = threadIdx.x;
  const int lane = tid & 31, wid = tid >> 5;
  const int wM = wid & 3, wN = wid >> 2;
  const int g = lane >> 2, tg = lane & 3;
  const int m0 = bx * 128, n0 = by * 64;
  const int ai0 = tid * 2, ai1 = tid * 2 + 1;
  const int ar0 = ai0 >> 2, ac0 = (ai0 & 3) * 4;
  const int ar1 = ai1 >> 2, ac1 = (ai1 & 3) * 4;
  const int bk = tid >> 4, bn = (tid & 15) * 4;

  {
    float4 a4 = *(const float4*)(A + (size_t)(m0 + ar0) * K + ac0);
    As[ar0*20+ac0+0] = f2tf(a4.x); As[ar0*20+ac0+1] = f2tf(a4.y);
    As[ar0*20+ac0+2] = f2tf(a4.z); As[ar0*20+ac0+3] = f2tf(a4.w);
    a4 = *(const float4*)(A + (size_t)(m0 + ar1) * K + ac1);
    As[ar1*20+ac1+0] = f2tf(a4.x); As[ar1*20+ac1+1] = f2tf(a4.y);
    As[ar1*20+ac1+2] = f2tf(a4.z); As[ar1*20+ac1+3] = f2tf(a4.w);
    const float* br = Bm + (size_t)bk * N;
    const int c = n0 + bn;
    float4 b4;
    b4.x = (c+0 < N) ? br[c+0] : 0.f; b4.y = (c+1 < N) ? br[c+1] : 0.f;
    b4.z = (c+2 < N) ? br[c+2] : 0.f; b4.w = (c+3 < N) ? br[c+3] : 0.f;
    Bs[bk*68+bn+0] = f2tf(b4.x); Bs[bk*68+bn+1] = f2tf(b4.y);
    Bs[bk*68+bn+2] = f2tf(b4.z); Bs[bk*68+bn+3] = f2tf(b4.w);
  }
  __syncthreads();

  float4 acc[2][4];
#pragma unroll
  for (int mf = 0; mf < 2; mf++)
#pragma unroll
    for (int nf = 0; nf < 4; nf++) acc[mf][nf] = make_float4(0.f, 0.f, 0.f, 0.f);

  const int NT = K >> 4;
  for (int kt = 0; kt < NT; kt++) {
    const unsigned* Ac = As + (kt & 1) * 2560;
    const unsigned* Bc = Bs + (kt & 1) * 1088;
    float4 na0 = make_float4(0.f,0.f,0.f,0.f), na1 = na0, nb4 = na0;
    const bool has = (kt + 1 < NT);
    if (has) {
      na0 = *(const float4*)(A + (size_t)(m0 + ar0) * K + (kt + 1) * 16 + ac0);
      na1 = *(const float4*)(A + (size_t)(m0 + ar1) * K + (kt + 1) * 16 + ac1);
      const float* br = Bm + (size_t)((kt + 1) * 16 + bk) * N;
      const int c = n0 + bn;
      nb4.x = (c+0 < N) ? br[c+0] : 0.f; nb4.y = (c+1 < N) ? br[c+1] : 0.f;
      nb4.z = (c+2 < N) ? br[c+2] : 0.f; nb4.w = (c+3 < N) ? br[c+3] : 0.f;
    }
#pragma unroll
    for (int kb = 0; kb < 2; kb++) {
      const int kk = kb * 8;
      uint4 af[2];
#pragma unroll
      for (int mf = 0; mf < 2; mf++) {
        const int r = wM * 32 + mf * 16 + g;
        af[mf].x = Ac[ r      * 20 + kk + tg];
        af[mf].y = Ac[(r + 8) * 20 + kk + tg];
        af[mf].z = Ac[ r      * 20 + kk + tg + 4];
        af[mf].w = Ac[(r + 8) * 20 + kk + tg + 4];
      }
#pragma unroll
      for (int nf = 0; nf < 4; nf++) {
        const int n = wN * 32 + nf * 8 + g;
        const unsigned b0 = Bc[(kk + tg) * 68 + n];
        const unsigned b1 = Bc[(kk + tg + 4) * 68 + n];
#pragma unroll
        for (int mf = 0; mf < 2; mf++)
          mma8(acc[mf][nf], af[mf].x, af[mf].y, af[mf].z, af[mf].w, b0, b1);
      }
    }
    if (has) {
      unsigned* An = As + ((kt + 1) & 1) * 2560;
      unsigned* Bn = Bs + ((kt + 1) & 1) * 1088;
      An[ar0*20+ac0+0] = f2tf(na0.x); An[ar0*20+ac0+1] = f2tf(na0.y);
      An[ar0*20+ac0+2] = f2tf(na0.z); An[ar0*20+ac0+3] = f2tf(na0.w);
      An[ar1*20+ac1+0] = f2tf(na1.x); An[ar1*20+ac1+1] = f2tf(na1.y);
      An[ar1*20+ac1+2] = f2tf(na1.z); An[ar1*20+ac1+3] = f2tf(na1.w);
      Bn[bk*68+bn+0] = f2tf(nb4.x); Bn[bk*68+bn+1] = f2tf(nb4.y);
      Bn[bk*68+bn+2] = f2tf(nb4.z); Bn[bk*68+bn+3] = f2tf(nb4.w);
    }
    __syncthreads();
  }

#pragma unroll
  for (int mf = 0; mf < 2; mf++) {
    const int r1 = m0 + wM * 32 + mf * 16 + g, r2 = r1 + 8;
#pragma unroll
    for (int nf = 0; nf < 4; nf++) {
      const int c = n0 + wN * 32 + nf * 8 + 2 * tg;
      const float4 a = acc[mf][nf];
      if (c < N) {
        const float bv = bias[c];
        float v1 = a.x + bv, v2 = a.z + bv;
        if (RELU) { v1 = fmaxf(v1, 0.f); v2 = fmaxf(v2, 0.f); }
        if (TF32OUT) {
          ((unsigned*)Cv)[(size_t)r1 * N + c] = f2tf(v1 * oscale);
          ((unsigned*)Cv)[(size_t)r2 * N + c] = f2tf(v2 * oscale);
        } else {
          ((float*)Cv)[(size_t)r1 * N + c] = v1;
          ((float*)Cv)[(size_t)r2 * N + c] = v2;
        }
      }
      if (c + 1 < N) {
        const float bv = bias[c + 1];
        float v1 = a.y + bv, v2 = a.w + bv;
        if (RELU) { v1 = fmaxf(v1, 0.f); v2 = fmaxf(v2, 0.f); }
        if (TF32OUT) {
          ((unsigned*)Cv)[(size_t)r1 * N + c + 1] = f2tf(v1 * oscale);
          ((unsigned*)Cv)[(size_t)r2 * N + c + 1] = f2tf(v2 * oscale);
        } else {
          ((float*)Cv)[(size_t)r1 * N + c + 1] = v1;
          ((float*)Cv)[(size_t)r2 * N + c + 1] = v2;
        }
      }
    }
  }
}

__launch_bounds__(256)
__global__ void proj2(const float* __restrict__ q, const float* __restrict__ k,
                      const float* __restrict__ v,
                      const float* __restrict__ Wq, const float* __restrict__ bq,
                      const float* __restrict__ Wk, const float* __restrict__ bk2,
                      const float* __restrict__ Wv, const float* __restrict__ bv2,
                      unsigned* __restrict__ qh, unsigned* __restrict__ kh,
                      unsigned* __restrict__ vh) {
  __shared__ unsigned sm[7296];
  const float* A; const float* W; const float* Bi; unsigned* Cc; float sc;
  if (blockIdx.z == 0)      { A = q; W = Wq; Bi = bq;  Cc = qh; sc = 0.125f; }
  else if (blockIdx.z == 1) { A = k; W = Wk; Bi = bk2; Cc = kh; sc = 1.f; }
  else                      { A = v; W = Wv; Bi = bv2; Cc = vh; sc = 1.f; }
  gemm2_body<false, true>(A, W, Bi, Cc, B_*T_, HD, DM, sc, blockIdx.x, 0, sm);
}

// ================= gemm3: all-tf32-in, 3-stage cp.async ====================
// CTA 128x64, 8 warps 4(m)x2(n), warp m32 x n32, k16 per stage.
#define G3S 3648   // words per stage: A 128*20=2560 + B 16*68=1088
template<bool RELU, bool TF32OUT>
__launch_bounds__(256)
__global__ void gemm3(const unsigned* __restrict__ A, const unsigned* __restrict__ Bm,
                      const float* __restrict__ bias, void* __restrict__ Cv,
                      int M, int N, int Np, int K, float oscale) {
  __shared__ unsigned sm[3 * G3S];
  const int tid = threadIdx.x;
  const int lane = tid & 31, wid = tid >> 5;
  const int wM = wid & 3, wN = wid >> 2;
  const int g = lane >> 2, tg = lane & 3;
  const int m0 = blockIdx.x * 128, n0 = blockIdx.y * 64;
  const int ai0 = tid * 2, ai1 = ai0 + 1;
  const int ar0 = ai0 >> 2, ac0 = (ai0 & 3) * 4;
  const int ar1 = ai1 >> 2, ac1 = (ai1 & 3) * 4;
  const int bk = tid >> 4, bn = (tid & 15) * 4;
  const unsigned s_base = (unsigned)__cvta_generic_to_shared(sm);

  const int NT = K >> 4;
#define G3_ISSUE(KT) do {                                                     \
    const int _k0 = (KT) * 16;                                                \
    const unsigned _st = s_base + ((KT) % 3) * (G3S * 4);                     \
    cpa16(_st + (unsigned)(ar0*20+ac0)*4u, A + (size_t)(m0+ar0)*K + _k0+ac0); \
    cpa16(_st + (unsigned)(ar1*20+ac1)*4u, A + (size_t)(m0+ar1)*K + _k0+ac1); \
    cpa16(_st + (unsigned)(2560 + bk*68+bn)*4u,                               \
          Bm + (size_t)(_k0+bk)*Np + n0+bn);                                  \
  } while (0)

  G3_ISSUE(0); CPA_COMMIT();
  G3_ISSUE(1); CPA_COMMIT();

  float4 acc[2][4];
#pragma unroll
  for (int mf = 0; mf < 2; mf++)
#pragma unroll
    for (int nf = 0; nf < 4; nf++) acc[mf][nf] = make_float4(0.f, 0.f, 0.f, 0.f);

  for (int kt = 0; kt < NT; kt++) {
    CPA_WAIT(1);
    __syncthreads();
    if (kt + 2 < NT) G3_ISSUE(kt + 2);
    CPA_COMMIT();
    const unsigned* Ac = sm + (kt % 3) * G3S;
    const unsigned* Bc = Ac + 2560;
#pragma unroll
    for (int kb = 0; kb < 2; kb++) {
      const int kk = kb * 8;
      uint4 af[2];
#pragma unroll
      for (int mf = 0; mf < 2; mf++) {
        const int r = wM * 32 + mf * 16 + g;
        af[mf].x = Ac[ r      * 20 + kk + tg];
        af[mf].y = Ac[(r + 8) * 20 + kk + tg];
        af[mf].z = Ac[ r      * 20 + kk + tg + 4];
        af[mf].w = Ac[(r + 8) * 20 + kk + tg + 4];
      }
#pragma unroll
      for (int nf = 0; nf < 4; nf++) {
        const int n = wN * 32 + nf * 8 + g;
        const unsigned b0 = Bc[(kk + tg) * 68 + n];
        const unsigned b1 = Bc[(kk + tg + 4) * 68 + n];
#pragma unroll
        for (int mf = 0; mf < 2; mf++)
          mma8(acc[mf][nf], af[mf].x, af[mf].y, af[mf].z, af[mf].w, b0, b1);
      }
    }
  }

#pragma unroll
  for (int mf = 0; mf < 2; mf++) {
    const int r1 = m0 + wM * 32 + mf * 16 + g, r2 = r1 + 8;
#pragma unroll
    for (int nf = 0; nf < 4; nf++) {
      const int c = n0 + wN * 32 + nf * 8 + 2 * tg;
      const float4 a = acc[mf][nf];
      if (c < N) {
        const float bv = bias[c];
        float v1 = a.x + bv, v2 = a.z + bv;
        if (RELU) { v1 = fmaxf(v1, 0.f); v2 = fmaxf(v2, 0.f); }
        if (TF32OUT) {
          ((unsigned*)Cv)[(size_t)r1 * N + c] = f2tf(v1 * oscale);
          ((unsigned*)Cv)[(size_t)r2 * N + c] = f2tf(v2 * oscale);
        } else {
          ((float*)Cv)[(size_t)r1 * N + c] = v1;
          ((float*)Cv)[(size_t)r2 * N + c] = v2;
        }
      }
      if (c + 1 < N) {
        const float bv = bias[c + 1];
        float v1 = a.y + bv, v2 = a.w + bv;
        if (RELU) { v1 = fmaxf(v1, 0.f); v2 = fmaxf(v2, 0.f); }
        if (TF32OUT) {
          ((unsigned*)Cv)[(size_t)r1 * N + c + 1] = f2tf(v1 * oscale);
          ((unsigned*)Cv)[(size_t)r2 * N + c + 1] = f2tf(v2 * oscale);
        } else {
          ((float*)Cv)[(size_t)r1 * N + c + 1] = v1;
          ((float*)Cv)[(size_t)r2 * N + c + 1] = v2;
        }
      }
    }
  }
#undef G3_ISSUE
}

// ===================== attention: pipelined loads ==========================
struct QFrag { uint4 a[8][2]; };

// prologue-only chunk (self-contained load+wait): QE[t][r&255] = q[t]·E[h][r]
__device__ __forceinline__ void att_chunk_pro(const unsigned* __restrict__ Etf, unsigned* Es,
                                              float* QE, const QFrag& qf, int h, int cb,
                                              int wM, int wN, int g, int tg, int tid) {
  if (cb >= T_) return;
  const unsigned es_s = (unsigned)__cvta_generic_to_shared(Es);
#pragma unroll
  for (int p = 0; p < 8; p++) {
    const int j = p * 16 + (tid >> 4);
    const int d = (tid & 15) * 4;
    if (cb + j < T_)
      cpa16(es_s + (unsigned)(j * 68 + d) * 4u, Etf + ((size_t)(h * T_ + cb + j)) * HD + d);
    else
      *(uint4*)(Es + j * 68 + d) = make_uint4(0u, 0u, 0u, 0u);
  }
  cpa_wait_all();
  __syncthreads();
  float4 acc[2][4];
#pragma unroll
  for (int mf = 0; mf < 2; mf++)
#pragma unroll
    for (int nf = 0; nf < 4; nf++) acc[mf][nf] = make_float4(0.f, 0.f, 0.f, 0.f);
#pragma unroll
  for (int kb = 0; kb < 8; kb++) {
    const int kk = kb * 8;
#pragma unroll
    for (int nf = 0; nf < 4; nf++) {
      const int n = wN * 32 + nf * 8 + g;
      const unsigned b0 = Es[n * 68 + kk + tg];
      const unsigned b1 = Es[n * 68 + kk + tg + 4];
#pragma unroll
      for (int mf = 0; mf < 2; mf++)
        mma8(acc[mf][nf], qf.a[kb][mf].x, qf.a[kb][mf].y, qf.a[kb][mf].z, qf.a[kb][mf].w, b0, b1);
    }
  }
#pragma unroll
  for (int mf = 0; mf < 2; mf++) {
    const int tl = wM * 32 + mf * 16 + g;
#pragma unroll
    for (int nf = 0; nf < 4; nf++) {
      const int r = cb + wN * 32 + nf * 8 + 2 * tg;
      QE[ tl      * 260 + ( r      & 255)] = acc[mf][nf].x;
      QE[ tl      * 260 + ((r + 1) & 255)] = acc[mf][nf].y;
      QE[(tl + 8) * 260 + ( r      & 255)] = acc[mf][nf].z;
      QE[(tl + 8) * 260 + ((r + 1) & 255)] = acc[mf][nf].w;
    }
  }
  __syncthreads();
}

__launch_bounds__(256, 1)
__global__ void attn_kernel(const unsigned* __restrict__ qh, const unsigned* __restrict__ kh,
                            const unsigned* __restrict__ vh, const unsigned* __restrict__ Etf,
                            unsigned* __restrict__ ctx) {
  extern __shared__ unsigned smu[];
  unsigned* Qs = smu;                     // [64][68]
  unsigned* Ks = Qs + 4352;               // [128][68]
  unsigned* Vs = Ks + 8704;               // [128][68]
  unsigned* Ps = Vs + 8704;               // [64][132] P matrix
  unsigned* Es = Ps + 8448;               // [128][68] E chunk (dedicated)
  float*    QE = (float*)(Es + 8704);     // [64][260] ring
  float* sPmax = QE + 64 * 260;           // [4][64]
  float* sPsum = sPmax + 256;             // [4][64]

  const int tid = threadIdx.x;
  const int lane = tid & 31, wid = tid >> 5;
  const int wM = wid & 1, wN = wid >> 1;       // 2 x 4
  const int g = lane >> 2, tg = lane & 3;
  const int qt = (int)gridDim.x - 1 - (int)blockIdx.x;  // heavy tiles first
  const int t0 = qt * 64;
  const int b  = blockIdx.y;
  const int h  = blockIdx.z;

  // ---- load Q tile (tf32 bits, pre-scaled) ----
  {
    const unsigned qs_s = (unsigned)__cvta_generic_to_shared(Qs);
#pragma unroll
    for (int p = 0; p < 4; p++) {
      const int t = p * 16 + (tid >> 4);
      const int d = (tid & 15) * 4;
      cpa16(qs_s + (unsigned)(t * 68 + d) * 4u, qh + ((size_t)(b * T_ + t0 + t)) * HD + d);
    }
    cpa_wait_all();
  }
  __syncthreads();
  QFrag qf;
#pragma unroll
  for (int kb = 0; kb < 8; kb++) {
    const int c = kb * 8 + tg;
#pragma unroll
    for (int mf = 0; mf < 2; mf++) {
      const int row = wM * 32 + mf * 16 + g;
      qf.a[kb][mf].x = Qs[ row      * 68 + c];
      qf.a[kb][mf].y = Qs[(row + 8) * 68 + c];
      qf.a[kb][mf].z = Qs[ row      * 68 + c + 4];
      qf.a[kb][mf].w = Qs[(row + 8) * 68 + c + 4];
    }
  }

  const int wbase = T_ - 64 - t0;
  att_chunk_pro(Etf, Es, QE, qf, h, wbase,       wM, wN, g, tg, tid);
  att_chunk_pro(Etf, Es, QE, qf, h, wbase + 128, wM, wN, g, tg, tid);

  const unsigned ks_s = (unsigned)__cvta_generic_to_shared(Ks);
  const unsigned vs_s = (unsigned)__cvta_generic_to_shared(Vs);
  const unsigned es_s = (unsigned)__cvta_generic_to_shared(Es);
  const int ldp = tid >> 4;             // 0..15 row group for loads
  const int ldd = (tid & 15) * 4;       // col within row

  // ---- initial issues: group[KV(0)], group[Es(wbase+256)] ----
  {
#pragma unroll
    for (int p = 0; p < 8; p++) {
      const int e = p * 16 + ldp;
      const size_t gi = ((size_t)(b * T_ + e)) * HD + ldd;
      cpa16(ks_s + (unsigned)(e * 68 + ldd) * 4u, kh + gi);
      cpa16(vs_s + (unsigned)(e * 68 + ldd) * 4u, vh + gi);
    }
    CPA_COMMIT();
    const int cb = wbase + 256;
#pragma unroll
    for (int p = 0; p < 8; p++) {
      const int j = p * 16 + ldp;
      if (cb + j < T_)
        cpa16(es_s + (unsigned)(j * 68 + ldd) * 4u, Etf + ((size_t)(h * T_ + cb + j)) * HD + ldd);
      else
        *(uint4*)(Es + j * 68 + ldd) = make_uint4(0u, 0u, 0u, 0u);
    }
    CPA_COMMIT();
  }

  int trow[4];
  trow[0] = wM * 32 + g;      trow[1] = trow[0] + 8;
  trow[2] = trow[0] + 16;     trow[3] = trow[0] + 24;

  float mrun[4], lrun[4];
  float4 O[2][2];
#pragma unroll
  for (int i = 0; i < 4; i++) { mrun[i] = -1e30f; lrun[i] = 0.f; }
#pragma unroll
  for (int mf = 0; mf < 2; mf++)
#pragma unroll
    for (int nf = 0; nf < 2; nf++) O[mf][nf] = make_float4(0.f, 0.f, 0.f, 0.f);

  const int ns = (t0 + 64 + 127) >> 7;
  int cnext = wbase + 256;
  for (int it = 0; it < ns; it++) {
    const int s0 = it * 128;
    CPA_WAIT(1);        // K(it), V(it) complete
    __syncthreads();    // (A)

    // ---- QK ----
    float4 acc[2][4];
#pragma unroll
    for (int mf = 0; mf < 2; mf++)
#pragma unroll
      for (int nf = 0; nf < 4; nf++) acc[mf][nf] = make_float4(0.f, 0.f, 0.f, 0.f);
#pragma unroll
    for (int kb = 0; kb < 8; kb++) {
      const int kk = kb * 8;
#pragma unroll
      for (int nf = 0; nf < 4; nf++) {
        const int n = wN * 32 + nf * 8 + g;
        const unsigned b0 = Ks[n * 68 + kk + tg];
        const unsigned b1 = Ks[n * 68 + kk + tg + 4];
#pragma unroll
        for (int mf = 0; mf < 2; mf++)
          mma8(acc[mf][nf], qf.a[kb][mf].x, qf.a[kb][mf].y, qf.a[kb][mf].z, qf.a[kb][mf].w, b0, b1);
      }
    }

    // ---- bias + causal mask + local row max ----
    float mx[4] = {-1e30f, -1e30f, -1e30f, -1e30f};
#pragma unroll
    for (int mf = 0; mf < 2; mf++) {
      const int tA = t0 + trow[mf * 2];
      const int tB = t0 + trow[mf * 2 + 1];
#pragma unroll
      for (int nf = 0; nf < 4; nf++) {
        const int s = s0 + wN * 32 + nf * 8 + 2 * tg;
        float4& a = acc[mf][nf];
        const float q0 = QE[ trow[mf*2]    * 260 + ((s     - tA + 2047) & 255)];
        const float q1 = QE[ trow[mf*2]    * 260 + ((s + 1 - tA + 2047) & 255)];
        const float q2 = QE[ trow[mf*2+1]  * 260 + ((s     - tB + 2047) & 255)];
        const float q3 = QE[ trow[mf*2+1]  * 260 + ((s + 1 - tB + 2047) & 255)];
        a.x = (s     <= tA) ? a.x + q0 : -1e30f;
        a.y = (s + 1 <= tA) ? a.y + q1 : -1e30f;
        a.z = (s     <= tB) ? a.z + q2 : -1e30f;
        a.w = (s + 1 <= tB) ? a.w + q3 : -1e30f;
        mx[mf*2]   = fmaxf(mx[mf*2],   fmaxf(a.x, a.y));
        mx[mf*2+1] = fmaxf(mx[mf*2+1], fmaxf(a.z, a.w));
      }
    }
#pragma unroll
    for (int i = 0; i < 4; i++) {
      mx[i] = fmaxf(mx[i], __shfl_xor_sync(0xffffffffu, mx[i], 1));
      mx[i] = fmaxf(mx[i], __shfl_xor_sync(0xffffffffu, mx[i], 2));
    }
    if (tg == 0) {
#pragma unroll
      for (int i = 0; i < 4; i++) sPmax[wN * 64 + trow[i]] = mx[i];
    }
    __syncthreads();    // (B) — Ks fully consumed

    // prefetch K(it+1)
    if (it + 1 < ns) {
      const int s1 = s0 + 128;
#pragma unroll
      for (int p = 0; p < 8; p++) {
        const int e = p * 16 + ldp;
        cpa16(ks_s + (unsigned)(e * 68 + ldd) * 4u,
              kh + ((size_t)(b * T_ + s1 + e)) * HD + ldd);
      }
    }
    CPA_COMMIT();

    float Mrow[4], alpha[4];
#pragma unroll
    for (int i = 0; i < 4; i++) {
      float M = mrun[i];
      M = fmaxf(M, sPmax[       trow[i]]);
      M = fmaxf(M, sPmax[ 64  + trow[i]]);
      M = fmaxf(M, sPmax[128  + trow[i]]);
      M = fmaxf(M, sPmax[192  + trow[i]]);
      alpha[i] = __expf(mrun[i] - M);
      mrun[i] = M;
      Mrow[i] = M;
    }

    float sm4[4] = {0.f, 0.f, 0.f, 0.f};
#pragma unroll
    for (int mf = 0; mf < 2; mf++) {
#pragma unroll
      for (int nf = 0; nf < 4; nf++) {
        float4& a = acc[mf][nf];
        const int col = wN * 32 + nf * 8 + 2 * tg;
        const float p0 = __expf(a.x - Mrow[mf*2]);
        const float p1 = __expf(a.y - Mrow[mf*2]);
        const float p2 = __expf(a.z - Mrow[mf*2+1]);
        const float p3 = __expf(a.w - Mrow[mf*2+1]);
        sm4[mf*2]   += p0 + p1;
        sm4[mf*2+1] += p2 + p3;
        Ps[ trow[mf*2]    * 132 + col    ] = f2tf(p0);
        Ps[ trow[mf*2]    * 132 + col + 1] = f2tf(p1);
        Ps[ trow[mf*2+1]  * 132 + col    ] = f2tf(p2);
        Ps[ trow[mf*2+1]  * 132 + col + 1] = f2tf(p3);
      }
    }
#pragma unroll
    for (int i = 0; i < 4; i++) {
      sm4[i] += __shfl_xor_sync(0xffffffffu, sm4[i], 1);
      sm4[i] += __shfl_xor_sync(0xffffffffu, sm4[i], 2);
    }
    if (tg == 0) {
#pragma unroll
      for (int i = 0; i < 4; i++) sPsum[wN * 64 + trow[i]] = sm4[i];
    }
    CPA_WAIT(1);        // V(it) + Es(it) complete (K(it+1) still in flight)
    __syncthreads();    // (C)
#pragma unroll
    for (int i = 0; i < 4; i++) {
      lrun[i] = lrun[i] * alpha[i]
              + sPsum[trow[i]] + sPsum[64 + trow[i]]
              + sPsum[128 + trow[i]] + sPsum[192 + trow[i]];
    }
#pragma unroll
    for (int mf = 0; mf < 2; mf++)
#pragma unroll
      for (int nf = 0; nf < 2; nf++) {
        O[mf][nf].x *= alpha[mf*2];   O[mf][nf].y *= alpha[mf*2];
        O[mf][nf].z *= alpha[mf*2+1]; O[mf][nf].w *= alpha[mf*2+1];
      }

    // ---- PV ----
#pragma unroll
    for (int kb = 0; kb < 16; kb++) {
      const int kk = kb * 8;
#pragma unroll
      for (int mf = 0; mf < 2; mf++) {
        const int r0 = trow[mf * 2];
        const unsigned a0 = Ps[ r0      * 132 + kk + tg];
        const unsigned a1 = Ps[(r0 + 8) * 132 + kk + tg];
        const unsigned a2 = Ps[ r0      * 132 + kk + tg + 4];
        const unsigned a3 = Ps[(r0 + 8) * 132 + kk + tg + 4];
#pragma unroll
        for (int nf = 0; nf < 2; nf++) {
          const int n = wN * 16 + nf * 8 + g;
          mma8(O[mf][nf], a0, a1, a2, a3, Vs[(kk + tg) * 68 + n], Vs[(kk + tg + 4) * 68 + n]);
        }
      }
    }

    // ---- chunk MMA for cnext (reads Es, writes ring) ----
    if (cnext < T_) {
      float4 cacc[2][4];
#pragma unroll
      for (int mf = 0; mf < 2; mf++)
#pragma unroll
        for (int nf = 0; nf < 4; nf++) cacc[mf][nf] = make_float4(0.f, 0.f, 0.f, 0.f);
#pragma unroll
      for (int kb = 0; kb < 8; kb++) {
        const int kk = kb * 8;
#pragma unroll
        for (int nf = 0; nf < 4; nf++) {
          const int n = wN * 32 + nf * 8 + g;
          const unsigned b0 = Es[n * 68 + kk + tg];
          const unsigned b1 = Es[n * 68 + kk + tg + 4];
#pragma unroll
          for (int mf = 0; mf < 2; mf++)
            mma8(cacc[mf][nf], qf.a[kb][mf].x, qf.a[kb][mf].y, qf.a[kb][mf].z, qf.a[kb][mf].w, b0, b1);
        }
      }
#pragma unroll
      for (int mf = 0; mf < 2; mf++) {
        const int tl = wM * 32 + mf * 16 + g;
#pragma unroll
        for (int nf = 0; nf < 4; nf++) {
          const int r = cnext + wN * 32 + nf * 8 + 2 * tg;
          QE[ tl      * 260 + ( r      & 255)] = cacc[mf][nf].x;
          QE[ tl      * 260 + ((r + 1) & 255)] = cacc[mf][nf].y;
          QE[(tl + 8) * 260 + ( r      & 255)] = cacc[mf][nf].z;
          QE[(tl + 8) * 260 + ((r + 1) & 255)] = cacc[mf][nf].w;
        }
      }
    }
    __syncthreads();    // (D) — Vs, Es consumed; ring writes published by next (A)

    // prefetch V(it+1) + Es(cnext+128)
    if (it + 1 < ns) {
      const int s1 = s0 + 128;
#pragma unroll
      for (int p = 0; p < 8; p++) {
        const int e = p * 16 + ldp;
        cpa16(vs_s + (unsigned)(e * 68 + ldd) * 4u,
              vh + ((size_t)(b * T_ + s1 + e)) * HD + ldd);
      }
      const int cb2 = cnext + 128;
#pragma unroll
      for (int p = 0; p < 8; p++) {
        const int j = p * 16 + ldp;
        if (cb2 + j < T_)
          cpa16(es_s + (unsigned)(j * 68 + ldd) * 4u,
                Etf + ((size_t)(h * T_ + cb2 + j)) * HD + ldd);
        else
          *(uint4*)(Es + j * 68 + ldd) = make_uint4(0u, 0u, 0u, 0u);
      }
    }
    CPA_COMMIT();
    cnext += 128;
  }

  // ---- epilogue: tf32 ctx out ----
  float inv[4];
#pragma unroll
  for (int i = 0; i < 4; i++) inv[i] = 1.f / lrun[i];
#pragma unroll
  for (int mf = 0; mf < 2; mf++) {
    const int tA = t0 + trow[mf * 2];
    const int tB = t0 + trow[mf * 2 + 1];
#pragma unroll
    for (int nf = 0; nf < 2; nf++) {
      const int c = h * HD + wN * 16 + nf * 8 + 2 * tg;
      uint2 o1 = make_uint2(f2tf(O[mf][nf].x * inv[mf*2]),   f2tf(O[mf][nf].y * inv[mf*2]));
      uint2 o2 = make_uint2(f2tf(O[mf][nf].z * inv[mf*2+1]), f2tf(O[mf][nf].w * inv[mf*2+1]));
      *(uint2*)&ctx[((size_t)(b * T_ + tA)) * DM + c] = o1;
      *(uint2*)&ctx[((size_t)(b * T_ + tB)) * DM + c] = o2;
    }
  }
}

// ---------------------------------------------------------------------------
extern "C" void kernel_launch(void* const* d_in, const int* in_sizes, int n_in,
                              void* d_out, int out_size) {
  const float* v  = (const float*)d_in[0];
  const float* k  = (const float*)d_in[1];
  const float* q  = (const float*)d_in[2];
  // d_in[3] = mask (causal tril; implicit)
  const float* Wq = (const float*)d_in[4];
  const float* bq = (const float*)d_in[5];
  const float* Wk = (const float*)d_in[6];
  const float* bk = (const float*)d_in[7];
  const float* Wv = (const float*)d_in[8];
  const float* bv = (const float*)d_in[9];
  const float* E  = (const float*)d_in[10];
  const float* Wo = (const float*)d_in[11];
  const float* bo = (const float*)d_in[12];
  const float* Wl = (const float*)d_in[13];
  const float* bl = (const float*)d_in[14];
  float* out = (float*)d_out;

  unsigned *qh, *kh, *vh, *Etf, *Wotf, *Wltf, *ctx, *hid;
  cudaGetSymbolAddress((void**)&qh,   g_qh);
  cudaGetSymbolAddress((void**)&kh,   g_kh);
  cudaGetSymbolAddress((void**)&vh,   g_vh);
  cudaGetSymbolAddress((void**)&Etf,  g_Etf);
  cudaGetSymbolAddress((void**)&Wotf, g_Wotf);
  cudaGetSymbolAddress((void**)&Wltf, g_Wltf);
  cudaGetSymbolAddress((void**)&ctx,  g_ctx);
  cudaGetSymbolAddress((void**)&hid,  g_hid);

  const int M = B_ * T_;
  dim3 blk(256);

  cvt4_kernel<<<NH * T_ * HD / 4 / 256, blk>>>(E, Etf, NH * T_ * HD / 4);
  cvt4_kernel<<<DM * ED / 4 / 256, blk>>>(Wo, Wotf, DM * ED / 4);
  cvtpad_kernel<<<ED * EVP / 256, blk>>>(Wl, Wltf);
  proj2<<<dim3(M / 128, 1, 3), blk>>>(q, k, v, Wq, bq, Wk, bk, Wv, bv, qh, kh, vh);

  // smem words: Qs 4352 + Ks 8704 + Vs 8704 + Ps 8448 + Es 8704 + QE 16640 + red 512
  const size_t ATT_SMEM = (size_t)(4352 + 8704 + 8704 + 8448 + 8704 + 16640 + 512) * 4; // 224256 B
  cudaFuncSetAttribute(attn_kernel, cudaFuncAttributeMaxDynamicSharedMemorySize,
                       (int)ATT_SMEM);
  attn_kernel<<<dim3(T_ / 64, B_, NH), blk, ATT_SMEM>>>(qh, kh, vh, Etf, ctx);

  gemm3<true,  true ><<<dim3(M / 128, ED / 64), blk>>>(ctx, Wotf, bo, hid, M, ED, ED, DM, 1.f);
  gemm3<false, false><<<dim3(M / 128, EVP / 64), blk>>>(hid, Wltf, bl, out, M, EV, EVP, ED, 1.f);
}

// round 7
// speedup vs baseline: 2.9694x; 1.0142x over previous
#include <cuda_runtime.h>
#include <cstdint>

#define B_  2
#define T_  2048
#define HD  64
#define NH  8
#define DM  512
#define ED  512
#define EV  388
#define EVP 448      // Wl padded width

// ---------------- scratch ----------------
__device__ unsigned g_qh  [B_*T_*HD];   // tf32 bits, pre-scaled by 0.125
__device__ unsigned g_kh  [B_*T_*HD];   // tf32 bits
__device__ unsigned g_vh  [B_*T_*HD];   // tf32 bits
__device__ unsigned g_Etf [NH*T_*HD];   // tf32 bits
__device__ unsigned g_Wotf[DM*ED];      // tf32 bits
__device__ unsigned g_Wltf[ED*EVP];     // tf32 bits, zero-padded cols
__device__ unsigned g_ctx [B_*T_*DM];   // tf32 bits (attn out)
__device__ unsigned g_hid [B_*T_*ED];   // tf32 bits (relu out)

// ---------------- tf32 / async helpers ----------------
__device__ __forceinline__ unsigned f2tf(float f) {
  unsigned u; asm("cvt.rna.tf32.f32 %0, %1;" : "=r"(u) : "f"(f)); return u;
}
__device__ __forceinline__ unsigned u2tf(unsigned raw) {
  return f2tf(__uint_as_float(raw));
}
__device__ __forceinline__ void mma8(float4& d, unsigned a0, unsigned a1, unsigned a2, unsigned a3,
                                     unsigned b0, unsigned b1) {
  asm volatile("mma.sync.aligned.m16n8k8.row.col.f32.tf32.tf32.f32 "
               "{%0,%1,%2,%3}, {%4,%5,%6,%7}, {%8,%9}, {%0,%1,%2,%3};"
               : "+f"(d.x), "+f"(d.y), "+f"(d.z), "+f"(d.w)
               : "r"(a0), "r"(a1), "r"(a2), "r"(a3), "r"(b0), "r"(b1));
}
__device__ __forceinline__ void cpa16(unsigned smem, const void* g) {
  asm volatile("cp.async.cg.shared.global [%0], [%1], 16;" :: "r"(smem), "l"(g));
}
#define CPA_COMMIT() asm volatile("cp.async.commit_group;")
#define CPA_WAIT(N)  asm volatile("cp.async.wait_group %0;" :: "n"(N) : "memory")
__device__ __forceinline__ void cpa_wait_all() {
  CPA_COMMIT(); CPA_WAIT(0);
}

// ---------------- one-shot converters ----------------
__global__ void cvt4_kernel(const float* __restrict__ s, unsigned* __restrict__ d, int n4) {
  const int i = blockIdx.x * 256 + threadIdx.x;
  if (i < n4) {
    float4 f = ((const float4*)s)[i];
    ((uint4*)d)[i] = make_uint4(f2tf(f.x), f2tf(f.y), f2tf(f.z), f2tf(f.w));
  }
}
__global__ void cvtpad_kernel(const float* __restrict__ s, unsigned* __restrict__ d) {
  const int i = blockIdx.x * 256 + threadIdx.x;   // over ED*EVP
  const int k = i / EVP, n = i % EVP;
  d[i] = (n < EV) ? f2tf(s[k * EV + n]) : 0u;
}

// ================= gemm3: all-tf32-in, 3-stage cp.async ====================
// CTA 128x64, 8 warps 4(m)x2(n), warp m32 x n32, k16 per stage.
#define G3S 3648   // words per stage: A 128*20=2560 + B 16*68=1088
template<bool RELU, bool TF32OUT>
__launch_bounds__(256)
__global__ void gemm3(const unsigned* __restrict__ A, const unsigned* __restrict__ Bm,
                      const float* __restrict__ bias, void* __restrict__ Cv,
                      int M, int N, int Np, int K, float oscale) {
  __shared__ unsigned sm[3 * G3S];
  const int tid = threadIdx.x;
  const int lane = tid & 31, wid = tid >> 5;
  const int wM = wid & 3, wN = wid >> 2;
  const int g = lane >> 2, tg = lane & 3;
  const int m0 = blockIdx.x * 128, n0 = blockIdx.y * 64;
  const int ai0 = tid * 2, ai1 = ai0 + 1;
  const int ar0 = ai0 >> 2, ac0 = (ai0 & 3) * 4;
  const int ar1 = ai1 >> 2, ac1 = (ai1 & 3) * 4;
  const int bk = tid >> 4, bn = (tid & 15) * 4;
  const unsigned s_base = (unsigned)__cvta_generic_to_shared(sm);

  const int NT = K >> 4;
#define G3_ISSUE(KT) do {                                                     \
    const int _k0 = (KT) * 16;                                                \
    const unsigned _st = s_base + ((KT) % 3) * (G3S * 4);                     \
    cpa16(_st + (unsigned)(ar0*20+ac0)*4u, A + (size_t)(m0+ar0)*K + _k0+ac0); \
    cpa16(_st + (unsigned)(ar1*20+ac1)*4u, A + (size_t)(m0+ar1)*K + _k0+ac1); \
    cpa16(_st + (unsigned)(2560 + bk*68+bn)*4u,                               \
          Bm + (size_t)(_k0+bk)*Np + n0+bn);                                  \
  } while (0)

  G3_ISSUE(0); CPA_COMMIT();
  G3_ISSUE(1); CPA_COMMIT();

  float4 acc[2][4];
#pragma unroll
  for (int mf = 0; mf < 2; mf++)
#pragma unroll
    for (int nf = 0; nf < 4; nf++) acc[mf][nf] = make_float4(0.f, 0.f, 0.f, 0.f);

  for (int kt = 0; kt < NT; kt++) {
    CPA_WAIT(1);
    __syncthreads();
    if (kt + 2 < NT) G3_ISSUE(kt + 2);
    CPA_COMMIT();
    const unsigned* Ac = sm + (kt % 3) * G3S;
    const unsigned* Bc = Ac + 2560;
#pragma unroll
    for (int kb = 0; kb < 2; kb++) {
      const int kk = kb * 8;
      uint4 af[2];
#pragma unroll
      for (int mf = 0; mf < 2; mf++) {
        const int r = wM * 32 + mf * 16 + g;
        af[mf].x = Ac[ r      * 20 + kk + tg];
        af[mf].y = Ac[(r + 8) * 20 + kk + tg];
        af[mf].z = Ac[ r      * 20 + kk + tg + 4];
        af[mf].w = Ac[(r + 8) * 20 + kk + tg + 4];
      }
#pragma unroll
      for (int nf = 0; nf < 4; nf++) {
        const int n = wN * 32 + nf * 8 + g;
        const unsigned b0 = Bc[(kk + tg) * 68 + n];
        const unsigned b1 = Bc[(kk + tg + 4) * 68 + n];
#pragma unroll
        for (int mf = 0; mf < 2; mf++)
          mma8(acc[mf][nf], af[mf].x, af[mf].y, af[mf].z, af[mf].w, b0, b1);
      }
    }
  }

#pragma unroll
  for (int mf = 0; mf < 2; mf++) {
    const int r1 = m0 + wM * 32 + mf * 16 + g, r2 = r1 + 8;
#pragma unroll
    for (int nf = 0; nf < 4; nf++) {
      const int c = n0 + wN * 32 + nf * 8 + 2 * tg;
      const float4 a = acc[mf][nf];
      if (c < N) {
        const float bv = bias[c];
        float v1 = a.x + bv, v2 = a.z + bv;
        if (RELU) { v1 = fmaxf(v1, 0.f); v2 = fmaxf(v2, 0.f); }
        if (TF32OUT) {
          ((unsigned*)Cv)[(size_t)r1 * N + c] = f2tf(v1 * oscale);
          ((unsigned*)Cv)[(size_t)r2 * N + c] = f2tf(v2 * oscale);
        } else {
          ((float*)Cv)[(size_t)r1 * N + c] = v1;
          ((float*)Cv)[(size_t)r2 * N + c] = v2;
        }
      }
      if (c + 1 < N) {
        const float bv = bias[c + 1];
        float v1 = a.y + bv, v2 = a.w + bv;
        if (RELU) { v1 = fmaxf(v1, 0.f); v2 = fmaxf(v2, 0.f); }
        if (TF32OUT) {
          ((unsigned*)Cv)[(size_t)r1 * N + c + 1] = f2tf(v1 * oscale);
          ((unsigned*)Cv)[(size_t)r2 * N + c + 1] = f2tf(v2 * oscale);
        } else {
          ((float*)Cv)[(size_t)r1 * N + c + 1] = v1;
          ((float*)Cv)[(size_t)r2 * N + c + 1] = v2;
        }
      }
    }
  }
#undef G3_ISSUE
}

// ================= proj3: pipelined q/k/v projection (fp32 in, cvt at LDS) =
// CTA 128x64 (N=HD=64 exactly), 8 warps 4(m)x2(n); 3-stage cp.async on RAW
// fp32 A and B tiles; cvt.rna applied when fragments are loaded from smem.
__launch_bounds__(256)
__global__ void proj3(const float* __restrict__ q, const float* __restrict__ k,
                      const float* __restrict__ v,
                      const float* __restrict__ Wq, const float* __restrict__ bq,
                      const float* __restrict__ Wk, const float* __restrict__ bk2,
                      const float* __restrict__ Wv, const float* __restrict__ bv2,
                      unsigned* __restrict__ qh, unsigned* __restrict__ kh,
                      unsigned* __restrict__ vh) {
  __shared__ unsigned sm[3 * G3S];
  const float* A; const float* Bm; const float* Bi; unsigned* Cc; float sc;
  if (blockIdx.z == 0)      { A = q; Bm = Wq; Bi = bq;  Cc = qh; sc = 0.125f; }
  else if (blockIdx.z == 1) { A = k; Bm = Wk; Bi = bk2; Cc = kh; sc = 1.f; }
  else                      { A = v; Bm = Wv; Bi = bv2; Cc = vh; sc = 1.f; }

  const int tid = threadIdx.x;
  const int lane = tid & 31, wid = tid >> 5;
  const int wM = wid & 3, wN = wid >> 2;
  const int g = lane >> 2, tg = lane & 3;
  const int m0 = blockIdx.x * 128;
  const int ai0 = tid * 2, ai1 = ai0 + 1;
  const int ar0 = ai0 >> 2, ac0 = (ai0 & 3) * 4;
  const int ar1 = ai1 >> 2, ac1 = (ai1 & 3) * 4;
  const int bk = tid >> 4, bn = (tid & 15) * 4;
  const unsigned s_base = (unsigned)__cvta_generic_to_shared(sm);

  const int NT = DM >> 4;   // 32
#define P3_ISSUE(KT) do {                                                       \
    const int _k0 = (KT) * 16;                                                  \
    const unsigned _st = s_base + ((KT) % 3) * (G3S * 4);                       \
    cpa16(_st + (unsigned)(ar0*20+ac0)*4u, A + (size_t)(m0+ar0)*DM + _k0+ac0);  \
    cpa16(_st + (unsigned)(ar1*20+ac1)*4u, A + (size_t)(m0+ar1)*DM + _k0+ac1);  \
    cpa16(_st + (unsigned)(2560 + bk*68+bn)*4u, Bm + (size_t)(_k0+bk)*HD + bn); \
  } while (0)

  P3_ISSUE(0); CPA_COMMIT();
  P3_ISSUE(1); CPA_COMMIT();

  float4 acc[2][4];
#pragma unroll
  for (int mf = 0; mf < 2; mf++)
#pragma unroll
    for (int nf = 0; nf < 4; nf++) acc[mf][nf] = make_float4(0.f, 0.f, 0.f, 0.f);

  for (int kt = 0; kt < NT; kt++) {
    CPA_WAIT(1);
    __syncthreads();
    if (kt + 2 < NT) P3_ISSUE(kt + 2);
    CPA_COMMIT();
    const unsigned* Ac = sm + (kt % 3) * G3S;
    const unsigned* Bc = Ac + 2560;
#pragma unroll
    for (int kb = 0; kb < 2; kb++) {
      const int kk = kb * 8;
      uint4 af[2];
#pragma unroll
      for (int mf = 0; mf < 2; mf++) {
        const int r = wM * 32 + mf * 16 + g;
        af[mf].x = u2tf(Ac[ r      * 20 + kk + tg]);
        af[mf].y = u2tf(Ac[(r + 8) * 20 + kk + tg]);
        af[mf].z = u2tf(Ac[ r      * 20 + kk + tg + 4]);
        af[mf].w = u2tf(Ac[(r + 8) * 20 + kk + tg + 4]);
      }
#pragma unroll
      for (int nf = 0; nf < 4; nf++) {
        const int n = wN * 32 + nf * 8 + g;
        const unsigned b0 = u2tf(Bc[(kk + tg) * 68 + n]);
        const unsigned b1 = u2tf(Bc[(kk + tg + 4) * 68 + n]);
#pragma unroll
        for (int mf = 0; mf < 2; mf++)
          mma8(acc[mf][nf], af[mf].x, af[mf].y, af[mf].z, af[mf].w, b0, b1);
      }
    }
  }

#pragma unroll
  for (int mf = 0; mf < 2; mf++) {
    const int r1 = m0 + wM * 32 + mf * 16 + g, r2 = r1 + 8;
#pragma unroll
    for (int nf = 0; nf < 4; nf++) {
      const int c = wN * 32 + nf * 8 + 2 * tg;   // always < 64
      const float4 a = acc[mf][nf];
      const float bv0 = Bi[c], bv1 = Bi[c + 1];
      Cc[(size_t)r1 * HD + c]     = f2tf((a.x + bv0) * sc);
      Cc[(size_t)r2 * HD + c]     = f2tf((a.z + bv0) * sc);
      Cc[(size_t)r1 * HD + c + 1] = f2tf((a.y + bv1) * sc);
      Cc[(size_t)r2 * HD + c + 1] = f2tf((a.w + bv1) * sc);
    }
  }
#undef P3_ISSUE
}

// ===================== attention: pipelined loads (verified r6) ============
struct QFrag { uint4 a[8][2]; };

__device__ __forceinline__ void att_chunk_pro(const unsigned* __restrict__ Etf, unsigned* Es,
                                              float* QE, const QFrag& qf, int h, int cb,
                                              int wM, int wN, int g, int tg, int tid) {
  if (cb >= T_) return;
  const unsigned es_s = (unsigned)__cvta_generic_to_shared(Es);
#pragma unroll
  for (int p = 0; p < 8; p++) {
    const int j = p * 16 + (tid >> 4);
    const int d = (tid & 15) * 4;
    if (cb + j < T_)
      cpa16(es_s + (unsigned)(j * 68 + d) * 4u, Etf + ((size_t)(h * T_ + cb + j)) * HD + d);
    else
      *(uint4*)(Es + j * 68 + d) = make_uint4(0u, 0u, 0u, 0u);
  }
  cpa_wait_all();
  __syncthreads();
  float4 acc[2][4];
#pragma unroll
  for (int mf = 0; mf < 2; mf++)
#pragma unroll
    for (int nf = 0; nf < 4; nf++) acc[mf][nf] = make_float4(0.f, 0.f, 0.f, 0.f);
#pragma unroll
  for (int kb = 0; kb < 8; kb++) {
    const int kk = kb * 8;
#pragma unroll
    for (int nf = 0; nf < 4; nf++) {
      const int n = wN * 32 + nf * 8 + g;
      const unsigned b0 = Es[n * 68 + kk + tg];
      const unsigned b1 = Es[n * 68 + kk + tg + 4];
#pragma unroll
      for (int mf = 0; mf < 2; mf++)
        mma8(acc[mf][nf], qf.a[kb][mf].x, qf.a[kb][mf].y, qf.a[kb][mf].z, qf.a[kb][mf].w, b0, b1);
    }
  }
#pragma unroll
  for (int mf = 0; mf < 2; mf++) {
    const int tl = wM * 32 + mf * 16 + g;
#pragma unroll
    for (int nf = 0; nf < 4; nf++) {
      const int r = cb + wN * 32 + nf * 8 + 2 * tg;
      QE[ tl      * 260 + ( r      & 255)] = acc[mf][nf].x;
      QE[ tl      * 260 + ((r + 1) & 255)] = acc[mf][nf].y;
      QE[(tl + 8) * 260 + ( r      & 255)] = acc[mf][nf].z;
      QE[(tl + 8) * 260 + ((r + 1) & 255)] = acc[mf][nf].w;
    }
  }
  __syncthreads();
}

__launch_bounds__(256, 1)
__global__ void attn_kernel(const unsigned* __restrict__ qh, const unsigned* __restrict__ kh,
                            const unsigned* __restrict__ vh, const unsigned* __restrict__ Etf,
                            unsigned* __restrict__ ctx) {
  extern __shared__ unsigned smu[];
  unsigned* Qs = smu;                     // [64][68]
  unsigned* Ks = Qs + 4352;               // [128][68]
  unsigned* Vs = Ks + 8704;               // [128][68]
  unsigned* Ps = Vs + 8704;               // [64][132] P matrix
  unsigned* Es = Ps + 8448;               // [128][68] E chunk (dedicated)
  float*    QE = (float*)(Es + 8704);     // [64][260] ring
  float* sPmax = QE + 64 * 260;           // [4][64]
  float* sPsum = sPmax + 256;             // [4][64]

  const int tid = threadIdx.x;
  const int lane = tid & 31, wid = tid >> 5;
  const int wM = wid & 1, wN = wid >> 1;       // 2 x 4
  const int g = lane >> 2, tg = lane & 3;
  const int qt = (int)gridDim.x - 1 - (int)blockIdx.x;  // heavy tiles first
  const int t0 = qt * 64;
  const int b  = blockIdx.y;
  const int h  = blockIdx.z;

  {
    const unsigned qs_s = (unsigned)__cvta_generic_to_shared(Qs);
#pragma unroll
    for (int p = 0; p < 4; p++) {
      const int t = p * 16 + (tid >> 4);
      const int d = (tid & 15) * 4;
      cpa16(qs_s + (unsigned)(t * 68 + d) * 4u, qh + ((size_t)(b * T_ + t0 + t)) * HD + d);
    }
    cpa_wait_all();
  }
  __syncthreads();
  QFrag qf;
#pragma unroll
  for (int kb = 0; kb < 8; kb++) {
    const int c = kb * 8 + tg;
#pragma unroll
    for (int mf = 0; mf < 2; mf++) {
      const int row = wM * 32 + mf * 16 + g;
      qf.a[kb][mf].x = Qs[ row      * 68 + c];
      qf.a[kb][mf].y = Qs[(row + 8) * 68 + c];
      qf.a[kb][mf].z = Qs[ row      * 68 + c + 4];
      qf.a[kb][mf].w = Qs[(row + 8) * 68 + c + 4];
    }
  }

  const int wbase = T_ - 64 - t0;
  att_chunk_pro(Etf, Es, QE, qf, h, wbase,       wM, wN, g, tg, tid);
  att_chunk_pro(Etf, Es, QE, qf, h, wbase + 128, wM, wN, g, tg, tid);

  const unsigned ks_s = (unsigned)__cvta_generic_to_shared(Ks);
  const unsigned vs_s = (unsigned)__cvta_generic_to_shared(Vs);
  const unsigned es_s = (unsigned)__cvta_generic_to_shared(Es);
  const int ldp = tid >> 4;
  const int ldd = (tid & 15) * 4;

  {
#pragma unroll
    for (int p = 0; p < 8; p++) {
      const int e = p * 16 + ldp;
      const size_t gi = ((size_t)(b * T_ + e)) * HD + ldd;
      cpa16(ks_s + (unsigned)(e * 68 + ldd) * 4u, kh + gi);
      cpa16(vs_s + (unsigned)(e * 68 + ldd) * 4u, vh + gi);
    }
    CPA_COMMIT();
    const int cb = wbase + 256;
#pragma unroll
    for (int p = 0; p < 8; p++) {
      const int j = p * 16 + ldp;
      if (cb + j < T_)
        cpa16(es_s + (unsigned)(j * 68 + ldd) * 4u, Etf + ((size_t)(h * T_ + cb + j)) * HD + ldd);
      else
        *(uint4*)(Es + j * 68 + ldd) = make_uint4(0u, 0u, 0u, 0u);
    }
    CPA_COMMIT();
  }

  int trow[4];
  trow[0] = wM * 32 + g;      trow[1] = trow[0] + 8;
  trow[2] = trow[0] + 16;     trow[3] = trow[0] + 24;

  float mrun[4], lrun[4];
  float4 O[2][2];
#pragma unroll
  for (int i = 0; i < 4; i++) { mrun[i] = -1e30f; lrun[i] = 0.f; }
#pragma unroll
  for (int mf = 0; mf < 2; mf++)
#pragma unroll
    for (int nf = 0; nf < 2; nf++) O[mf][nf] = make_float4(0.f, 0.f, 0.f, 0.f);

  const int ns = (t0 + 64 + 127) >> 7;
  int cnext = wbase + 256;
  for (int it = 0; it < ns; it++) {
    const int s0 = it * 128;
    CPA_WAIT(1);
    __syncthreads();    // (A)

    float4 acc[2][4];
#pragma unroll
    for (int mf = 0; mf < 2; mf++)
#pragma unroll
      for (int nf = 0; nf < 4; nf++) acc[mf][nf] = make_float4(0.f, 0.f, 0.f, 0.f);
#pragma unroll
    for (int kb = 0; kb < 8; kb++) {
      const int kk = kb * 8;
#pragma unroll
      for (int nf = 0; nf < 4; nf++) {
        const int n = wN * 32 + nf * 8 + g;
        const unsigned b0 = Ks[n * 68 + kk + tg];
        const unsigned b1 = Ks[n * 68 + kk + tg + 4];
#pragma unroll
        for (int mf = 0; mf < 2; mf++)
          mma8(acc[mf][nf], qf.a[kb][mf].x, qf.a[kb][mf].y, qf.a[kb][mf].z, qf.a[kb][mf].w, b0, b1);
      }
    }

    float mx[4] = {-1e30f, -1e30f, -1e30f, -1e30f};
#pragma unroll
    for (int mf = 0; mf < 2; mf++) {
      const int tA = t0 + trow[mf * 2];
      const int tB = t0 + trow[mf * 2 + 1];
#pragma unroll
      for (int nf = 0; nf < 4; nf++) {
        const int s = s0 + wN * 32 + nf * 8 + 2 * tg;
        float4& a = acc[mf][nf];
        const float q0 = QE[ trow[mf*2]    * 260 + ((s     - tA + 2047) & 255)];
        const float q1 = QE[ trow[mf*2]    * 260 + ((s + 1 - tA + 2047) & 255)];
        const float q2 = QE[ trow[mf*2+1]  * 260 + ((s     - tB + 2047) & 255)];
        const float q3 = QE[ trow[mf*2+1]  * 260 + ((s + 1 - tB + 2047) & 255)];
        a.x = (s     <= tA) ? a.x + q0 : -1e30f;
        a.y = (s + 1 <= tA) ? a.y + q1 : -1e30f;
        a.z = (s     <= tB) ? a.z + q2 : -1e30f;
        a.w = (s + 1 <= tB) ? a.w + q3 : -1e30f;
        mx[mf*2]   = fmaxf(mx[mf*2],   fmaxf(a.x, a.y));
        mx[mf*2+1] = fmaxf(mx[mf*2+1], fmaxf(a.z, a.w));
      }
    }
#pragma unroll
    for (int i = 0; i < 4; i++) {
      mx[i] = fmaxf(mx[i], __shfl_xor_sync(0xffffffffu, mx[i], 1));
      mx[i] = fmaxf(mx[i], __shfl_xor_sync(0xffffffffu, mx[i], 2));
    }
    if (tg == 0) {
#pragma unroll
      for (int i = 0; i < 4; i++) sPmax[wN * 64 + trow[i]] = mx[i];
    }
    __syncthreads();    // (B)

    if (it + 1 < ns) {
      const int s1 = s0 + 128;
#pragma unroll
      for (int p = 0; p < 8; p++) {
        const int e = p * 16 + ldp;
        cpa16(ks_s + (unsigned)(e * 68 + ldd) * 4u,
              kh + ((size_t)(b * T_ + s1 + e)) * HD + ldd);
      }
    }
    CPA_COMMIT();

    float Mrow[4], alpha[4];
#pragma unroll
    for (int i = 0; i < 4; i++) {
      float M = mrun[i];
      M = fmaxf(M, sPmax[       trow[i]]);
      M = fmaxf(M, sPmax[ 64  + trow[i]]);
      M = fmaxf(M, sPmax[128  + trow[i]]);
      M = fmaxf(M, sPmax[192  + trow[i]]);
      alpha[i] = __expf(mrun[i] - M);
      mrun[i] = M;
      Mrow[i] = M;
    }

    float sm4[4] = {0.f, 0.f, 0.f, 0.f};
#pragma unroll
    for (int mf = 0; mf < 2; mf++) {
#pragma unroll
      for (int nf = 0; nf < 4; nf++) {
        float4& a = acc[mf][nf];
        const int col = wN * 32 + nf * 8 + 2 * tg;
        const float p0 = __expf(a.x - Mrow[mf*2]);
        const float p1 = __expf(a.y - Mrow[mf*2]);
        const float p2 = __expf(a.z - Mrow[mf*2+1]);
        const float p3 = __expf(a.w - Mrow[mf*2+1]);
        sm4[mf*2]   += p0 + p1;
        sm4[mf*2+1] += p2 + p3;
        Ps[ trow[mf*2]    * 132 + col    ] = f2tf(p0);
        Ps[ trow[mf*2]    * 132 + col + 1] = f2tf(p1);
        Ps[ trow[mf*2+1]  * 132 + col    ] = f2tf(p2);
        Ps[ trow[mf*2+1]  * 132 + col + 1] = f2tf(p3);
      }
    }
#pragma unroll
    for (int i = 0; i < 4; i++) {
      sm4[i] += __shfl_xor_sync(0xffffffffu, sm4[i], 1);
      sm4[i] += __shfl_xor_sync(0xffffffffu, sm4[i], 2);
    }
    if (tg == 0) {
#pragma unroll
      for (int i = 0; i < 4; i++) sPsum[wN * 64 + trow[i]] = sm4[i];
    }
    CPA_WAIT(1);
    __syncthreads();    // (C)
#pragma unroll
    for (int i = 0; i < 4; i++) {
      lrun[i] = lrun[i] * alpha[i]
              + sPsum[trow[i]] + sPsum[64 + trow[i]]
              + sPsum[128 + trow[i]] + sPsum[192 + trow[i]];
    }
#pragma unroll
    for (int mf = 0; mf < 2; mf++)
#pragma unroll
      for (int nf = 0; nf < 2; nf++) {
        O[mf][nf].x *= alpha[mf*2];   O[mf][nf].y *= alpha[mf*2];
        O[mf][nf].z *= alpha[mf*2+1]; O[mf][nf].w *= alpha[mf*2+1];
      }

#pragma unroll
    for (int kb = 0; kb < 16; kb++) {
      const int kk = kb * 8;
#pragma unroll
      for (int mf = 0; mf < 2; mf++) {
        const int r0 = trow[mf * 2];
        const unsigned a0 = Ps[ r0      * 132 + kk + tg];
        const unsigned a1 = Ps[(r0 + 8) * 132 + kk + tg];
        const unsigned a2 = Ps[ r0      * 132 + kk + tg + 4];
        const unsigned a3 = Ps[(r0 + 8) * 132 + kk + tg + 4];
#pragma unroll
        for (int nf = 0; nf < 2; nf++) {
          const int n = wN * 16 + nf * 8 + g;
          mma8(O[mf][nf], a0, a1, a2, a3, Vs[(kk + tg) * 68 + n], Vs[(kk + tg + 4) * 68 + n]);
        }
      }
    }

    if (cnext < T_) {
      float4 cacc[2][4];
#pragma unroll
      for (int mf = 0; mf < 2; mf++)
#pragma unroll
        for (int nf = 0; nf < 4; nf++) cacc[mf][nf] = make_float4(0.f, 0.f, 0.f, 0.f);
#pragma unroll
      for (int kb = 0; kb < 8; kb++) {
        const int kk = kb * 8;
#pragma unroll
        for (int nf = 0; nf < 4; nf++) {
          const int n = wN * 32 + nf * 8 + g;
          const unsigned b0 = Es[n * 68 + kk + tg];
          const unsigned b1 = Es[n * 68 + kk + tg + 4];
#pragma unroll
          for (int mf = 0; mf < 2; mf++)
            mma8(cacc[mf][nf], qf.a[kb][mf].x, qf.a[kb][mf].y, qf.a[kb][mf].z, qf.a[kb][mf].w, b0, b1);
        }
      }
#pragma unroll
      for (int mf = 0; mf < 2; mf++) {
        const int tl = wM * 32 + mf * 16 + g;
#pragma unroll
        for (int nf = 0; nf < 4; nf++) {
          const int r = cnext + wN * 32 + nf * 8 + 2 * tg;
          QE[ tl      * 260 + ( r      & 255)] = cacc[mf][nf].x;
          QE[ tl      * 260 + ((r + 1) & 255)] = cacc[mf][nf].y;
          QE[(tl + 8) * 260 + ( r      & 255)] = cacc[mf][nf].z;
          QE[(tl + 8) * 260 + ((r + 1) & 255)] = cacc[mf][nf].w;
        }
      }
    }
    __syncthreads();    // (D)

    if (it + 1 < ns) {
      const int s1 = s0 + 128;
#pragma unroll
      for (int p = 0; p < 8; p++) {
        const int e = p * 16 + ldp;
        cpa16(vs_s + (unsigned)(e * 68 + ldd) * 4u,
              vh + ((size_t)(b * T_ + s1 + e)) * HD + ldd);
      }
      const int cb2 = cnext + 128;
#pragma unroll
      for (int p = 0; p < 8; p++) {
        const int j = p * 16 + ldp;
        if (cb2 + j < T_)
          cpa16(es_s + (unsigned)(j * 68 + ldd) * 4u,
                Etf + ((size_t)(h * T_ + cb2 + j)) * HD + ldd);
        else
          *(uint4*)(Es + j * 68 + ldd) = make_uint4(0u, 0u, 0u, 0u);
      }
    }
    CPA_COMMIT();
    cnext += 128;
  }

  float inv[4];
#pragma unroll
  for (int i = 0; i < 4; i++) inv[i] = 1.f / lrun[i];
#pragma unroll
  for (int mf = 0; mf < 2; mf++) {
    const int tA = t0 + trow[mf * 2];
    const int tB = t0 + trow[mf * 2 + 1];
#pragma unroll
    for (int nf = 0; nf < 2; nf++) {
      const int c = h * HD + wN * 16 + nf * 8 + 2 * tg;
      uint2 o1 = make_uint2(f2tf(O[mf][nf].x * inv[mf*2]),   f2tf(O[mf][nf].y * inv[mf*2]));
      uint2 o2 = make_uint2(f2tf(O[mf][nf].z * inv[mf*2+1]), f2tf(O[mf][nf].w * inv[mf*2+1]));
      *(uint2*)&ctx[((size_t)(b * T_ + tA)) * DM + c] = o1;
      *(uint2*)&ctx[((size_t)(b * T_ + tB)) * DM + c] = o2;
    }
  }
}

// ---------------------------------------------------------------------------
extern "C" void kernel_launch(void* const* d_in, const int* in_sizes, int n_in,
                              void* d_out, int out_size) {
  const float* v  = (const float*)d_in[0];
  const float* k  = (const float*)d_in[1];
  const float* q  = (const float*)d_in[2];
  // d_in[3] = mask (causal tril; implicit)
  const float* Wq = (const float*)d_in[4];
  const float* bq = (const float*)d_in[5];
  const float* Wk = (const float*)d_in[6];
  const float* bk = (const float*)d_in[7];
  const float* Wv = (const float*)d_in[8];
  const float* bv = (const float*)d_in[9];
  const float* E  = (const float*)d_in[10];
  const float* Wo = (const float*)d_in[11];
  const float* bo = (const float*)d_in[12];
  const float* Wl = (const float*)d_in[13];
  const float* bl = (const float*)d_in[14];
  float* out = (float*)d_out;

  unsigned *qh, *kh, *vh, *Etf, *Wotf, *Wltf, *ctx, *hid;
  cudaGetSymbolAddress((void**)&qh,   g_qh);
  cudaGetSymbolAddress((void**)&kh,   g_kh);
  cudaGetSymbolAddress((void**)&vh,   g_vh);
  cudaGetSymbolAddress((void**)&Etf,  g_Etf);
  cudaGetSymbolAddress((void**)&Wotf, g_Wotf);
  cudaGetSymbolAddress((void**)&Wltf, g_Wltf);
  cudaGetSymbolAddress((void**)&ctx,  g_ctx);
  cudaGetSymbolAddress((void**)&hid,  g_hid);

  const int M = B_ * T_;
  dim3 blk(256);

  cvt4_kernel<<<NH * T_ * HD / 4 / 256, blk>>>(E, Etf, NH * T_ * HD / 4);
  cvt4_kernel<<<DM * ED / 4 / 256, blk>>>(Wo, Wotf, DM * ED / 4);
  cvtpad_kernel<<<ED * EVP / 256, blk>>>(Wl, Wltf);
  proj3<<<dim3(M / 128, 1, 3), blk>>>(q, k, v, Wq, bq, Wk, bk, Wv, bv, qh, kh, vh);

  // smem words: Qs 4352 + Ks 8704 + Vs 8704 + Ps 8448 + Es 8704 + QE 16640 + red 512
  const size_t ATT_SMEM = (size_t)(4352 + 8704 + 8704 + 8448 + 8704 + 16640 + 512) * 4; // 224256 B
  cudaFuncSetAttribute(attn_kernel, cudaFuncAttributeMaxDynamicSharedMemorySize,
                       (int)ATT_SMEM);
  attn_kernel<<<dim3(T_ / 64, B_, NH), blk, ATT_SMEM>>>(qh, kh, vh, Etf, ctx);

  gemm3<true,  true ><<<dim3(M / 128, ED / 64), blk>>>(ctx, Wotf, bo, hid, M, ED, ED, DM, 1.f);
  gemm3<false, false><<<dim3(M / 128, EVP / 64), blk>>>(hid, Wltf, bl, out, M, EV, EVP, ED, 1.f);
}